// round 14
// baseline (speedup 1.0000x reference)
#include <cuda_runtime.h>
#include <cuda_bf16.h>
#include <cuda_fp16.h>
#include <math.h>
#include <string.h>

#define NN   6144
#define G    24
#define DIN  128
#define DH   64
#define NH   8
#define QKV_W 1536

typedef unsigned long long u64;
typedef unsigned int u32;

// ---------------- device scratch --------------------------------------------
__device__ __half g_qkv[NN * QKV_W];           // 18.9 MB fp16 qkv
__device__ float g_h[NN * DH];
__device__ unsigned short g_xhi[NN * DIN];
__device__ unsigned short g_xlo[NN * DIN];
__device__ unsigned short g_whi[QKV_W * DIN];
__device__ unsigned short g_wlo[QKV_W * DIN];
__device__ float g_xs_part[96 * DIN];
__device__ float g_xq_part[96 * DIN];
__device__ float g_hsum[DH];
__device__ float g_hsumsq[DH];

// ---------------- PTX helpers -----------------------------------------------
__device__ __forceinline__ u32 smem_u32(const void* p) {
    u32 a;
    asm("{ .reg .u64 t; cvta.to.shared.u64 t, %1; cvt.u32.u64 %0, t; }"
        : "=r"(a) : "l"(p));
    return a;
}
__device__ __forceinline__ void ldsm_x4(u32& r0, u32& r1, u32& r2, u32& r3, u32 addr) {
    asm volatile("ldmatrix.sync.aligned.m8n8.x4.shared.b16 {%0,%1,%2,%3}, [%4];"
                 : "=r"(r0), "=r"(r1), "=r"(r2), "=r"(r3) : "r"(addr));
}
__device__ __forceinline__ void ldsm_x2(u32& r0, u32& r1, u32 addr) {
    asm volatile("ldmatrix.sync.aligned.m8n8.x2.shared.b16 {%0,%1}, [%2];"
                 : "=r"(r0), "=r"(r1) : "r"(addr));
}
__device__ __forceinline__ void mma_bf16(float* d, const u32* a, const u32* b) {
    asm volatile(
        "mma.sync.aligned.m16n8k16.row.col.f32.bf16.bf16.f32 "
        "{%0,%1,%2,%3},{%4,%5,%6,%7},{%8,%9},{%0,%1,%2,%3};"
        : "+f"(d[0]), "+f"(d[1]), "+f"(d[2]), "+f"(d[3])
        : "r"(a[0]), "r"(a[1]), "r"(a[2]), "r"(a[3]), "r"(b[0]), "r"(b[1]));
}
__device__ __forceinline__ u64 pack2(float lo, float hi) {
    u64 r; asm("mov.b64 %0,{%1,%2};" : "=l"(r) : "f"(lo), "f"(hi)); return r;
}
__device__ __forceinline__ u64 fma2(u64 a, u64 b, u64 c) {
    u64 d; asm("fma.rn.f32x2 %0,%1,%2,%3;" : "=l"(d) : "l"(a), "l"(b), "l"(c)); return d;
}
__device__ __forceinline__ void unpack2(u64 v, float& lo, float& hi) {
    asm("mov.b64 {%0,%1},%2;" : "=f"(lo), "=f"(hi) : "l"(v));
}
__device__ __forceinline__ void cvt8(uint4 u, float4& a, float4& b) {
    float2 p0 = __half22float2(*(__half2*)&u.x);
    float2 p1 = __half22float2(*(__half2*)&u.y);
    float2 p2 = __half22float2(*(__half2*)&u.z);
    float2 p3 = __half22float2(*(__half2*)&u.w);
    a = make_float4(p0.x, p0.y, p1.x, p1.y);
    b = make_float4(p2.x, p2.y, p3.x, p3.y);
}

__device__ __forceinline__ unsigned short bf16bits(float v) {
    __nv_bfloat16 b = __float2bfloat16(v);
    unsigned short s; memcpy(&s, &b, 2); return s;
}
__device__ __forceinline__ float bf16val(float v) {
    return __bfloat162float(__float2bfloat16(v));
}

// ---------------- K1: x stats partials --------------------------------------
__global__ void __launch_bounds__(256)
k_xstats(const float* __restrict__ x) {
    __shared__ float smS[8 * 128], smQ[8 * 128];
    int t  = threadIdx.x;
    int c4 = t & 31;
    int rs = t >> 5;
    int r0 = blockIdx.x * 64;

    const float4* xg = (const float4*)x;
    float4 s = make_float4(0.f, 0.f, 0.f, 0.f);
    float4 q = make_float4(0.f, 0.f, 0.f, 0.f);
    #pragma unroll
    for (int r = rs; r < 64; r += 8) {
        float4 v = xg[(size_t)(r0 + r) * 32 + c4];
        s.x += v.x; s.y += v.y; s.z += v.z; s.w += v.w;
        q.x += v.x * v.x; q.y += v.y * v.y; q.z += v.z * v.z; q.w += v.w * v.w;
    }
    ((float4*)smS)[rs * 32 + c4] = s;
    ((float4*)smQ)[rs * 32 + c4] = q;
    __syncthreads();
    if (t < 128) {
        float ss = 0.f, qq = 0.f;
        #pragma unroll
        for (int j = 0; j < 8; j++) { ss += smS[j * 128 + t]; qq += smQ[j * 128 + t]; }
        g_xs_part[blockIdx.x * 128 + t] = ss;
        g_xq_part[blockIdx.x * 128 + t] = qq;
    }
}

// ---------------- K2: normalize x -> bf16 hi/lo; W -> bf16 hi/lo; h init ----
__global__ void __launch_bounds__(256)
k_xnorm(const float* __restrict__ x,
        const float* __restrict__ nq_w, const float* __restrict__ nq_b,
        const float* __restrict__ nq_ms,
        const float* __restrict__ wq, const float* __restrict__ wk,
        const float* __restrict__ wv) {
    int tid = threadIdx.x;
    int b   = blockIdx.x;

    if (b == 0 && tid < DH) { g_hsum[tid] = 0.f; g_hsumsq[tid] = 0.f; }

    uint2* xh = (uint2*)g_xhi;
    uint2* xl = (uint2*)g_xlo;
    uint2* wh = (uint2*)g_whi;
    uint2* wl = (uint2*)g_wlo;

    if (b < 48) {
        __shared__ float As[128], Bs[128];
        if (tid < 128) {
            float ss = 0.f, qq = 0.f;
            #pragma unroll 8
            for (int p = 0; p < 96; p++) {
                ss += g_xs_part[p * 128 + tid];
                qq += g_xq_part[p * 128 + tid];
            }
            const float invN = 1.0f / NN;
            float mean = ss * invN;
            float ex2  = qq * invN;
            float mm   = mean * nq_ms[tid];
            float var  = ex2 - 2.f * mm * mean + mm * mm;
            float rinv = rsqrtf(var + 1e-5f);
            As[tid] = nq_w[tid] * rinv;
            Bs[tid] = nq_b[tid] - nq_w[tid] * rinv * mm;
        }
        __syncthreads();
        int r0 = b * 128;
        const float4* xg = (const float4*)x;
        for (int i = tid; i < 128 * 32; i += 256) {
            int row = i >> 5, c4 = i & 31, c = c4 * 4;
            float4 v = xg[(size_t)(r0 + row) * 32 + c4];
            float f[4];
            f[0] = fmaf(v.x, As[c],     Bs[c]);
            f[1] = fmaf(v.y, As[c + 1], Bs[c + 1]);
            f[2] = fmaf(v.z, As[c + 2], Bs[c + 2]);
            f[3] = fmaf(v.w, As[c + 3], Bs[c + 3]);
            unsigned short h[4], l[4];
            #pragma unroll
            for (int j = 0; j < 4; j++) {
                h[j] = bf16bits(f[j]);
                l[j] = bf16bits(f[j] - bf16val(f[j]));
            }
            uint2 uh, ul;
            uh.x = (u32)h[0] | ((u32)h[1] << 16); uh.y = (u32)h[2] | ((u32)h[3] << 16);
            ul.x = (u32)l[0] | ((u32)l[1] << 16); ul.y = (u32)l[2] | ((u32)l[3] << 16);
            size_t idx = (size_t)(r0 + row) * 32 + c4;
            xh[idx] = uh; xl[idx] = ul;
        }
        // residual init: g_h = x[:, :64] + x[:, 64:]
        float4* h4 = (float4*)g_h;
        for (int i = tid; i < 128 * 16; i += 256) {
            int row = i >> 4, c4 = i & 15;
            float4 xa = xg[(size_t)(r0 + row) * 32 + c4];
            float4 xb = xg[(size_t)(r0 + row) * 32 + 16 + c4];
            h4[(size_t)(r0 + row) * 16 + c4] =
                make_float4(xa.x + xb.x, xa.y + xb.y, xa.z + xb.z, xa.w + xb.w);
        }
    } else {
        int wr0 = (b - 48) * 128;
        for (int i = tid; i < 128 * 32; i += 256) {
            int row = i >> 5, c4 = i & 31;
            int gidx = wr0 + row;
            int mat = gidx >> 9, lr = gidx & 511;
            const float4* src = (const float4*)(mat == 0 ? wq : (mat == 1 ? wk : wv));
            float4 v = src[(size_t)lr * 32 + c4];
            float f[4] = {v.x, v.y, v.z, v.w};
            unsigned short h[4], l[4];
            #pragma unroll
            for (int j = 0; j < 4; j++) {
                h[j] = bf16bits(f[j]);
                l[j] = bf16bits(f[j] - bf16val(f[j]));
            }
            uint2 uh, ul;
            uh.x = (u32)h[0] | ((u32)h[1] << 16); uh.y = (u32)h[2] | ((u32)h[3] << 16);
            ul.x = (u32)l[0] | ((u32)l[1] << 16); ul.y = (u32)l[2] | ((u32)l[3] << 16);
            size_t idx = (size_t)gidx * 32 + c4;
            wh[idx] = uh; wl[idx] = ul;
        }
    }
}

// ---------------- K3: QKV GEMM via mma.sync bf16 split (hi+lo) --------------
#define ROWB 272
#define ATILE (128 * ROWB)
#define BTILE (64 * ROWB)
__global__ void __launch_bounds__(256, 2)
k_qkv(const float* __restrict__ bq, const float* __restrict__ bk,
      const float* __restrict__ bv) {
    extern __shared__ char smc[];
    float* bias_s = (float*)smc;
    char* aH = smc + 512;
    char* aL = aH + ATILE;
    char* bH = aL + ATILE;
    char* bL = bH + BTILE;

    int tid = threadIdx.x;
    int m0 = blockIdx.x * 128;
    int oc = blockIdx.y * 64;
    int mat = oc >> 9, o0 = oc & 511;
    const float* bias = mat == 0 ? bq : (mat == 1 ? bk : bv);
    if (tid < 64) bias_s[tid] = bias[o0 + tid];

    const uint4* xh4 = (const uint4*)g_xhi;   // 16 uint4 per 128-ch row
    const uint4* xl4 = (const uint4*)g_xlo;
    const uint4* wh4 = (const uint4*)g_whi;
    const uint4* wl4 = (const uint4*)g_wlo;

    #pragma unroll
    for (int i = tid; i < 2048; i += 256) {
        int row = i >> 4, c8 = i & 15;
        int so = row * ROWB + c8 * 16;
        size_t ax = (size_t)(m0 + row) * 16 + c8;
        *(uint4*)(aH + so) = xh4[ax];
        *(uint4*)(aL + so) = xl4[ax];
    }
    #pragma unroll
    for (int i = tid; i < 1024; i += 256) {
        int row = i >> 4, c8 = i & 15;
        int so = row * ROWB + c8 * 16;
        size_t bx = (size_t)(oc + row) * 16 + c8;
        *(uint4*)(bH + so) = wh4[bx];
        *(uint4*)(bL + so) = wl4[bx];
    }
    __syncthreads();

    u32 sb = smem_u32(smc);
    u32 aHb = sb + 512, aLb = aHb + ATILE, bHb = aLb + ATILE, bLb = bHb + BTILE;

    int t   = tid & 31;
    int wid = tid >> 5;
    int wm = (wid & 3) * 32;
    int wn = (wid >> 2) * 32;
    int rowA = ((t >> 3) & 1) * 8 + (t & 7);
    int kofA = (t >> 4) * 8;
    int rowB = (t & 7);
    int kofB = ((t >> 3) & 1) * 8;

    float acc[2][4][4];
    #pragma unroll
    for (int mf = 0; mf < 2; mf++)
        #pragma unroll
        for (int nf = 0; nf < 4; nf++)
            #pragma unroll
            for (int j = 0; j < 4; j++) acc[mf][nf][j] = 0.f;

    for (int k = 0; k < 128; k += 16) {
        u32 ah[2][4], al[2][4], bh[4][2], bl[4][2];
        #pragma unroll
        for (int mf = 0; mf < 2; mf++) {
            u32 off = (u32)((wm + mf * 16 + rowA) * ROWB + (k + kofA) * 2);
            ldsm_x4(ah[mf][0], ah[mf][1], ah[mf][2], ah[mf][3], aHb + off);
            ldsm_x4(al[mf][0], al[mf][1], al[mf][2], al[mf][3], aLb + off);
        }
        #pragma unroll
        for (int nf = 0; nf < 4; nf++) {
            u32 off = (u32)((wn + nf * 8 + rowB) * ROWB + (k + kofB) * 2);
            ldsm_x2(bh[nf][0], bh[nf][1], bHb + off);
            ldsm_x2(bl[nf][0], bl[nf][1], bLb + off);
        }
        #pragma unroll
        for (int mf = 0; mf < 2; mf++)
            #pragma unroll
            for (int nf = 0; nf < 4; nf++) {
                mma_bf16(acc[mf][nf], ah[mf], bh[nf]);
                mma_bf16(acc[mf][nf], ah[mf], bl[nf]);
                mma_bf16(acc[mf][nf], al[mf], bh[nf]);
            }
    }

    int tq = t >> 2, tr = t & 3;
    #pragma unroll
    for (int mf = 0; mf < 2; mf++) {
        int m = m0 + wm + mf * 16 + tq;
        #pragma unroll
        for (int nf = 0; nf < 4; nf++) {
            int ln = wn + nf * 8 + tr * 2;
            float b0 = bias_s[ln], b1 = bias_s[ln + 1];
            *(__half2*)(g_qkv + (size_t)m * QKV_W + oc + ln) =
                __floats2half2_rn(acc[mf][nf][0] + b0, acc[mf][nf][1] + b1);
            *(__half2*)(g_qkv + (size_t)(m + 8) * QKV_W + oc + ln) =
                __floats2half2_rn(acc[mf][nf][2] + b0, acc[mf][nf][3] + b1);
        }
    }
}

// ---------------- K4: attention, 2 heads per CTA; V kept fp16 in smem -------
// buf per head (uint4 units): q fp32 [0,408), kt fp32 [408,808), v fp16 [808,1024)
#define PBUF 1024
__global__ void __launch_bounds__(192, 6)
k_attn() {
    __shared__ float4 buf[2][PBUF];
    __shared__ __align__(16) float alphaT[2][24 * 24];   // [s][d]

    int tid = threadIdx.x;
    int set = blockIdx.x >> 2;
    int h0  = (blockIdx.x & 3) << 1;
    int n0  = set * G;

    const uint4* srcH = (const uint4*)g_qkv + (size_t)n0 * 192;  // 192 uint4/row
    #pragma unroll
    for (int p = 0; p < 2; p++) {
        int h = h0 + p;
        float4* q4h = buf[p];
        float4* kt4 = buf[p] + 408;
        uint4*  v16 = (uint4*)(buf[p] + 808);   // [24][9] raw fp16
        int n = tid >> 3, g = tid & 7;           // 192 items exactly
        uint4 uq = srcH[n * 192 + h * 8 + g];
        uint4 uk = srcH[n * 192 + 64 + h * 8 + g];
        uint4 uv = srcH[n * 192 + 128 + h * 8 + g];
        float4 f0, f1;
        cvt8(uq, f0, f1);
        q4h[n * 17 + 2 * g] = f0; q4h[n * 17 + 2 * g + 1] = f1;
        cvt8(uk, f0, f1);
        kt4[(2 * g) * 25 + n] = f0; kt4[(2 * g + 1) * 25 + n] = f1;
        v16[n * 9 + g] = uv;                     // raw fp16, no convert
    }
    __syncthreads();

    // logits: 192 threads = 2 heads x 96 (each: 2 d x 3 s), fp32 f32x2
    {
        int p = tid >= 96;
        int r = tid - p * 96;
        const ulonglong2* q8 = (const ulonglong2*)buf[p];
        const ulonglong2* k8 = (const ulonglong2*)(buf[p] + 408);
        float* aT = alphaT[p];
        int d0 = (r >> 3) * 2;
        int sg = r & 7;
        u64 a00 = 0, a01 = 0, a02 = 0, a10 = 0, a11 = 0, a12 = 0;
        #pragma unroll
        for (int j = 0; j < 16; j++) {
            ulonglong2 q0 = q8[d0 * 17 + j];
            ulonglong2 q1 = q8[(d0 + 1) * 17 + j];
            ulonglong2 k0 = k8[j * 25 + sg * 3];
            ulonglong2 k1 = k8[j * 25 + sg * 3 + 1];
            ulonglong2 k2 = k8[j * 25 + sg * 3 + 2];
            a00 = fma2(q0.x, k0.x, a00); a00 = fma2(q0.y, k0.y, a00);
            a01 = fma2(q0.x, k1.x, a01); a01 = fma2(q0.y, k1.y, a01);
            a02 = fma2(q0.x, k2.x, a02); a02 = fma2(q0.y, k2.y, a02);
            a10 = fma2(q1.x, k0.x, a10); a10 = fma2(q1.y, k0.y, a10);
            a11 = fma2(q1.x, k1.x, a11); a11 = fma2(q1.y, k1.y, a11);
            a12 = fma2(q1.x, k2.x, a12); a12 = fma2(q1.y, k2.y, a12);
        }
        float lo, hi;
        int s0 = sg * 3;
        unpack2(a00, lo, hi); aT[(s0 + 0) * 24 + d0]     = (lo + hi) * 0.125f;
        unpack2(a01, lo, hi); aT[(s0 + 1) * 24 + d0]     = (lo + hi) * 0.125f;
        unpack2(a02, lo, hi); aT[(s0 + 2) * 24 + d0]     = (lo + hi) * 0.125f;
        unpack2(a10, lo, hi); aT[(s0 + 0) * 24 + d0 + 1] = (lo + hi) * 0.125f;
        unpack2(a11, lo, hi); aT[(s0 + 1) * 24 + d0 + 1] = (lo + hi) * 0.125f;
        unpack2(a12, lo, hi); aT[(s0 + 2) * 24 + d0 + 1] = (lo + hi) * 0.125f;
    }
    __syncthreads();

    // softmax: 48 threads = 2 heads x 24 destinations
    if (tid < 48) {
        int p = tid / 24, d = tid - p * 24;
        float* aT = alphaT[p];
        float m = aT[d];
        #pragma unroll
        for (int s = 1; s < G; s++) m = fmaxf(m, aT[s * 24 + d]);
        float sum = 0.f;
        #pragma unroll
        for (int s = 0; s < G; s++) {
            float e = expf(aT[s * 24 + d] - m);
            aT[s * 24 + d] = e;
            sum += e;
        }
        float inv = 1.0f / (sum + 1e-16f);
        #pragma unroll
        for (int s = 0; s < G; s++) aT[s * 24 + d] *= inv;
    }
    __syncthreads();

    // aggregate: 96 threads = (12 d-pairs) x (8 ch-groups of 8); both heads
    if (tid < 96) {
        int dp = tid >> 3, cg = tid & 7;
        int d0 = dp * 2;
        u64 acc[2][4];
        #pragma unroll
        for (int i2 = 0; i2 < 2; i2++)
            #pragma unroll
            for (int w = 0; w < 4; w++) acc[i2][w] = 0ull;
        #pragma unroll
        for (int p = 0; p < 2; p++) {
            const uint4* v16 = (const uint4*)(buf[p] + 808);
            const float* aT = alphaT[p];
            #pragma unroll
            for (int s = 0; s < G; s++) {
                float2 al = *(const float2*)&aT[s * 24 + d0];
                uint4 vv = v16[s * 9 + cg];
                u64 vp[4];
                #pragma unroll
                for (int w = 0; w < 4; w++) {
                    float2 f = __half22float2(((const __half2*)&vv)[w]);
                    vp[w] = pack2(f.x, f.y);
                }
                u64 p0 = pack2(al.x, al.x), p1 = pack2(al.y, al.y);
                #pragma unroll
                for (int w = 0; w < 4; w++) {
                    acc[0][w] = fma2(p0, vp[w], acc[0][w]);
                    acc[1][w] = fma2(p1, vp[w], acc[1][w]);
                }
            }
        }
        #pragma unroll
        for (int i2 = 0; i2 < 2; i2++) {
            float* dst = g_h + (size_t)(n0 + d0 + i2) * DH + cg * 8;
            #pragma unroll
            for (int w = 0; w < 4; w++) {
                float x0, x1;
                unpack2(acc[i2][w], x0, x1);
                atomicAdd(dst + 2 * w + 0, x0 * 0.125f);
                atomicAdd(dst + 2 * w + 1, x1 * 0.125f);
            }
        }
    }
}

// ---------------- K5: h stats (96 blocks x 64 rows) -------------------------
__global__ void __launch_bounds__(256)
k_hstats() {
    __shared__ float smS[16 * 64], smQ[16 * 64];
    int t  = threadIdx.x;
    int c4 = t & 15;
    int rs = t >> 4;
    int r0 = blockIdx.x * 64;

    const float4* h4 = (const float4*)g_h;
    float4 s = make_float4(0.f, 0.f, 0.f, 0.f);
    float4 q = make_float4(0.f, 0.f, 0.f, 0.f);
    #pragma unroll
    for (int r = rs; r < 64; r += 16) {
        float4 a = h4[(size_t)(r0 + r) * 16 + c4];
        s.x += a.x; s.y += a.y; s.z += a.z; s.w += a.w;
        q.x += a.x * a.x; q.y += a.y * a.y; q.z += a.z * a.z; q.w += a.w * a.w;
    }
    ((float4*)smS)[rs * 16 + c4] = s;
    ((float4*)smQ)[rs * 16 + c4] = q;
    __syncthreads();
    if (t < 64) {
        float ss = 0.f, qq = 0.f;
        #pragma unroll
        for (int j = 0; j < 16; j++) { ss += smS[j * 64 + t]; qq += smQ[j * 64 + t]; }
        atomicAdd(&g_hsum[t], ss);
        atomicAdd(&g_hsumsq[t], qq);
    }
}

__device__ __forceinline__ float gelu_exact(float v) {
    return 0.5f * v * (1.0f + erff(v * 0.70710678118654752f));
}

// ---------------- K6: global norm + PFF + per-set norm + score + pooling ----
#define WPU 65
__global__ void __launch_bounds__(256)
k_final(const float* __restrict__ x,
        const float* __restrict__ no_w, const float* __restrict__ no_b,
        const float* __restrict__ no_ms,
        const float* __restrict__ o_w1, const float* __restrict__ o_b1,
        const float* __restrict__ o_w2, const float* __restrict__ o_b2,
        const float* __restrict__ pn_w, const float* __restrict__ pn_b,
        const float* __restrict__ pn_ms,
        const float* __restrict__ p_w1, const float* __restrict__ p_b1,
        const float* __restrict__ p_w2, const float* __restrict__ p_b2,
        float* __restrict__ out) {
    extern __shared__ float dsm[];
    u64*  w1P  = (u64*)dsm;
    u64*  w2P  = w1P + 32 * WPU;
    u64*  pw1P = w2P + 32 * WPU;
    u64*  pw2P = pw1P + 32 * WPU;
    float* hs  = (float*)(pw2P + 32);
    float* hn  = hs + G * DH;
    float* t1  = hn + G * DH;
    float* h2  = t1 + G * DH;
    float* a2  = h2 + G * DH;
    float* b2v = a2 + DH;
    float* cm  = b2v + DH;
    float* cr  = cm + DH;
    float* b1s = cr + DH;
    float* b2s = b1s + DH;
    float* pb1s = b2s + DH;
    float* score = pb1s + DH;
    float* wsf   = score + G;

    int tid = threadIdx.x;
    int n0  = blockIdx.x * G;

    for (int i = tid; i < 64 * 32; i += 256) {
        int j = i >> 5, c2 = i & 31;
        float2 w1v = *(const float2*)(o_w1 + j * 64 + c2 * 2);
        w1P[c2 * WPU + j] = pack2(w1v.x, w1v.y);
        float2 pw = *(const float2*)(p_w1 + j * 64 + c2 * 2);
        pw1P[c2 * WPU + j] = pack2(pw.x, pw.y);
        float2 w2v = *(const float2*)(o_w2 + j * 64 + c2 * 2);
        w2P[c2 * WPU + j] = pack2(w2v.x, w2v.y);
    }
    if (tid < 32) {
        pw2P[tid] = pack2(p_w2[tid * 2], p_w2[tid * 2 + 1]);
    }
    if (tid < DH) {
        b1s[tid] = o_b1[tid]; b2s[tid] = o_b2[tid];
        pb1s[tid] = p_b1[tid];
        const float invN = 1.0f / NN;
        float mean = g_hsum[tid] * invN;
        float ex2  = g_hsumsq[tid] * invN;
        float mm   = mean * no_ms[tid];
        float var  = ex2 - 2.f * mm * mean + mm * mm;
        float rinv = rsqrtf(var + 1e-5f);
        a2[tid] = no_w[tid] * rinv;
        b2v[tid] = no_b[tid] - no_w[tid] * rinv * mm;
    }
    for (int i = tid; i < G * DH; i += 256) hs[i] = g_h[(size_t)n0 * DH + i];
    __syncthreads();

    for (int i = tid; i < G * DH; i += 256) {
        int c = i & 63;
        hn[i] = fmaf(hs[i], a2[c], b2v[c]);
    }
    __syncthreads();

    for (int i = tid; i < 384; i += 256) {
        int dp = i >> 5, jp = i & 31, d0 = dp * 2;
        u64 A00 = 0, A01 = 0, A10 = 0, A11 = 0;
        const u64* h0 = (const u64*)(hn + d0 * DH);
        const u64* h1 = (const u64*)(hn + (d0 + 1) * DH);
        #pragma unroll 8
        for (int c2 = 0; c2 < 32; c2++) {
            u64 w0 = w1P[c2 * WPU + jp], w1 = w1P[c2 * WPU + jp + 32];
            u64 hc0 = h0[c2], hc1 = h1[c2];
            A00 = fma2(hc0, w0, A00); A01 = fma2(hc0, w1, A01);
            A10 = fma2(hc1, w0, A10); A11 = fma2(hc1, w1, A11);
        }
        float lo, hi;
        unpack2(A00, lo, hi); t1[d0 * DH + jp]            = gelu_exact(lo + hi + b1s[jp]);
        unpack2(A01, lo, hi); t1[d0 * DH + jp + 32]       = gelu_exact(lo + hi + b1s[jp + 32]);
        unpack2(A10, lo, hi); t1[(d0 + 1) * DH + jp]      = gelu_exact(lo + hi + b1s[jp]);
        unpack2(A11, lo, hi); t1[(d0 + 1) * DH + jp + 32] = gelu_exact(lo + hi + b1s[jp + 32]);
    }
    __syncthreads();

    for (int i = tid; i < 384; i += 256) {
        int dp = i >> 5, cp = i & 31, d0 = dp * 2;
        u64 A00 = 0, A01 = 0, A10 = 0, A11 = 0;
        const u64* t0 = (const u64*)(t1 + d0 * DH);
        const u64* t1r = (const u64*)(t1 + (d0 + 1) * DH);
        #pragma unroll 8
        for (int j2 = 0; j2 < 32; j2++) {
            u64 w0 = w2P[j2 * WPU + cp], w1 = w2P[j2 * WPU + cp + 32];
            u64 tc0 = t0[j2], tc1 = t1r[j2];
            A00 = fma2(tc0, w0, A00); A01 = fma2(tc0, w1, A01);
            A10 = fma2(tc1, w0, A10); A11 = fma2(tc1, w1, A11);
        }
        float lo, hi;
        unpack2(A00, lo, hi); h2[d0 * DH + cp]            = hs[d0 * DH + cp] + lo + hi + b2s[cp];
        unpack2(A01, lo, hi); h2[d0 * DH + cp + 32]       = hs[d0 * DH + cp + 32] + lo + hi + b2s[cp + 32];
        unpack2(A10, lo, hi); h2[(d0 + 1) * DH + cp]      = hs[(d0 + 1) * DH + cp] + lo + hi + b2s[cp];
        unpack2(A11, lo, hi); h2[(d0 + 1) * DH + cp + 32] = hs[(d0 + 1) * DH + cp + 32] + lo + hi + b2s[cp + 32];
    }
    __syncthreads();

    if (tid < DH) {
        int c = tid;
        float m = 0.f;
        #pragma unroll
        for (int d = 0; d < G; d++) m += h2[d * DH + c];
        m *= (1.0f / G);
        float mm = m * pn_ms[c];
        float vv = 0.f;
        #pragma unroll
        for (int d = 0; d < G; d++) { float t = h2[d * DH + c] - mm; vv += t * t; }
        vv *= (1.0f / G);
        cm[c] = mm;
        cr[c] = pn_w[c] * rsqrtf(vv + 1e-5f);
    }
    __syncthreads();

    for (int i = tid; i < G * DH; i += 256) {
        int c = i & 63;
        hn[i] = fmaf(h2[i] - cm[c], cr[c], pn_b[c]);
    }
    __syncthreads();

    for (int i = tid; i < 384; i += 256) {
        int dp = i >> 5, jp = i & 31, d0 = dp * 2;
        u64 A00 = 0, A01 = 0, A10 = 0, A11 = 0;
        const u64* h0 = (const u64*)(hn + d0 * DH);
        const u64* h1 = (const u64*)(hn + (d0 + 1) * DH);
        #pragma unroll 8
        for (int c2 = 0; c2 < 32; c2++) {
            u64 w0 = pw1P[c2 * WPU + jp], w1 = pw1P[c2 * WPU + jp + 32];
            u64 hc0 = h0[c2], hc1 = h1[c2];
            A00 = fma2(hc0, w0, A00); A01 = fma2(hc0, w1, A01);
            A10 = fma2(hc1, w0, A10); A11 = fma2(hc1, w1, A11);
        }
        float lo, hi;
        unpack2(A00, lo, hi); t1[d0 * DH + jp]            = gelu_exact(lo + hi + pb1s[jp]);
        unpack2(A01, lo, hi); t1[d0 * DH + jp + 32]       = gelu_exact(lo + hi + pb1s[jp + 32]);
        unpack2(A10, lo, hi); t1[(d0 + 1) * DH + jp]      = gelu_exact(lo + hi + pb1s[jp]);
        unpack2(A11, lo, hi); t1[(d0 + 1) * DH + jp + 32] = gelu_exact(lo + hi + pb1s[jp + 32]);
    }
    __syncthreads();

    if (tid < G) {
        const u64* tr = (const u64*)(t1 + tid * DH);
        u64 A = 0;
        #pragma unroll 8
        for (int j2 = 0; j2 < 32; j2++) A = fma2(tr[j2], pw2P[j2], A);
        float lo, hi;
        unpack2(A, lo, hi);
        score[tid] = lo + hi + p_b2[0];
    }
    __syncthreads();

    if (tid == 0) {
        float m = score[0];
        #pragma unroll
        for (int d = 1; d < G; d++) m = fmaxf(m, score[d]);
        float sum = 0.f;
        #pragma unroll
        for (int d = 0; d < G; d++) { wsf[d] = expf(score[d] - m); sum += wsf[d]; }
        float inv = 1.0f / (sum + 1e-16f);
        #pragma unroll
        for (int d = 0; d < G; d++) wsf[d] *= inv;
    }
    __syncthreads();

    if (tid < DIN) {
        float acc = 0.f;
        #pragma unroll
        for (int d = 0; d < G; d++)
            acc = fmaf(wsf[d], x[(size_t)(n0 + d) * DIN + tid], acc);
        out[blockIdx.x * DIN + tid] = acc;
    }
}

// ---------------- launch -----------------------------------------------------
extern "C" void kernel_launch(void* const* d_in, const int* in_sizes, int n_in,
                              void* d_out, int out_size) {
    const float* x     = (const float*)d_in[0];
    const float* nq_w  = (const float*)d_in[4];
    const float* nq_b  = (const float*)d_in[5];
    const float* nq_ms = (const float*)d_in[6];
    const float* wq    = (const float*)d_in[7];
    const float* bq    = (const float*)d_in[8];
    const float* wk    = (const float*)d_in[9];
    const float* bk    = (const float*)d_in[10];
    const float* wv    = (const float*)d_in[11];
    const float* bv    = (const float*)d_in[12];
    const float* no_w  = (const float*)d_in[13];
    const float* no_b  = (const float*)d_in[14];
    const float* no_ms = (const float*)d_in[15];
    const float* o_w1  = (const float*)d_in[16];
    const float* o_b1  = (const float*)d_in[17];
    const float* o_w2  = (const float*)d_in[18];
    const float* o_b2  = (const float*)d_in[19];
    const float* pn_w  = (const float*)d_in[20];
    const float* pn_b  = (const float*)d_in[21];
    const float* pn_ms = (const float*)d_in[22];
    const float* p_w1  = (const float*)d_in[23];
    const float* p_b1  = (const float*)d_in[24];
    const float* p_w2  = (const float*)d_in[25];
    const float* p_b2  = (const float*)d_in[26];
    float* out = (float*)d_out;

    const int smem_qkv = 512 + 2 * ATILE + 2 * BTILE;
    const int smem_fin = (3 * 32 * WPU + 32) * 8 + (4 * G * DH + 7 * DH + 2 * G) * 4;
    cudaFuncSetAttribute(k_qkv,   cudaFuncAttributeMaxDynamicSharedMemorySize, smem_qkv);
    cudaFuncSetAttribute(k_final, cudaFuncAttributeMaxDynamicSharedMemorySize, smem_fin);

    k_xstats<<<96, 256>>>(x);
    k_xnorm<<<60, 256>>>(x, nq_w, nq_b, nq_ms, wq, wk, wv);
    k_qkv<<<dim3(48, 24), 256, smem_qkv>>>(bq, bk, bv);
    k_attn<<<1024, 192>>>();
    k_hstats<<<96, 256>>>();
    k_final<<<256, 256, smem_fin>>>(x, no_w, no_b, no_ms,
                                    o_w1, o_b1, o_w2, o_b2,
                                    pn_w, pn_b, pn_ms,
                                    p_w1, p_b1, p_w2, p_b2, out);
}

// round 15
// speedup vs baseline: 1.0468x; 1.0468x over previous
#include <cuda_runtime.h>
#include <cuda_bf16.h>
#include <cuda_fp16.h>
#include <math.h>
#include <string.h>

#define NN   6144
#define G    24
#define DIN  128
#define DH   64
#define NH   8
#define QKV_W 1536

typedef unsigned long long u64;
typedef unsigned int u32;

// ---------------- device scratch --------------------------------------------
__device__ __half g_qkv[NN * QKV_W];           // 18.9 MB fp16 qkv
__device__ float g_h[NN * DH];
__device__ unsigned short g_xhi[NN * DIN];
__device__ unsigned short g_xlo[NN * DIN];
__device__ unsigned short g_whi[QKV_W * DIN];
__device__ unsigned short g_wlo[QKV_W * DIN];
__device__ float g_xs_part[96 * DIN];
__device__ float g_xq_part[96 * DIN];
__device__ float g_hsum[DH];
__device__ float g_hsumsq[DH];

// ---------------- PTX helpers -----------------------------------------------
__device__ __forceinline__ u32 smem_u32(const void* p) {
    u32 a;
    asm("{ .reg .u64 t; cvta.to.shared.u64 t, %1; cvt.u32.u64 %0, t; }"
        : "=r"(a) : "l"(p));
    return a;
}
__device__ __forceinline__ void ldsm_x4(u32& r0, u32& r1, u32& r2, u32& r3, u32 addr) {
    asm volatile("ldmatrix.sync.aligned.m8n8.x4.shared.b16 {%0,%1,%2,%3}, [%4];"
                 : "=r"(r0), "=r"(r1), "=r"(r2), "=r"(r3) : "r"(addr));
}
__device__ __forceinline__ void ldsm_x2(u32& r0, u32& r1, u32 addr) {
    asm volatile("ldmatrix.sync.aligned.m8n8.x2.shared.b16 {%0,%1}, [%2];"
                 : "=r"(r0), "=r"(r1) : "r"(addr));
}
__device__ __forceinline__ void mma_bf16(float* d, const u32* a, const u32* b) {
    asm volatile(
        "mma.sync.aligned.m16n8k16.row.col.f32.bf16.bf16.f32 "
        "{%0,%1,%2,%3},{%4,%5,%6,%7},{%8,%9},{%0,%1,%2,%3};"
        : "+f"(d[0]), "+f"(d[1]), "+f"(d[2]), "+f"(d[3])
        : "r"(a[0]), "r"(a[1]), "r"(a[2]), "r"(a[3]), "r"(b[0]), "r"(b[1]));
}
__device__ __forceinline__ u64 pack2(float lo, float hi) {
    u64 r; asm("mov.b64 %0,{%1,%2};" : "=l"(r) : "f"(lo), "f"(hi)); return r;
}
__device__ __forceinline__ u64 fma2(u64 a, u64 b, u64 c) {
    u64 d; asm("fma.rn.f32x2 %0,%1,%2,%3;" : "=l"(d) : "l"(a), "l"(b), "l"(c)); return d;
}
__device__ __forceinline__ void unpack2(u64 v, float& lo, float& hi) {
    asm("mov.b64 {%0,%1},%2;" : "=f"(lo), "=f"(hi) : "l"(v));
}
__device__ __forceinline__ void cvt8(uint4 u, float4& a, float4& b) {
    float2 p0 = __half22float2(*(__half2*)&u.x);
    float2 p1 = __half22float2(*(__half2*)&u.y);
    float2 p2 = __half22float2(*(__half2*)&u.z);
    float2 p3 = __half22float2(*(__half2*)&u.w);
    a = make_float4(p0.x, p0.y, p1.x, p1.y);
    b = make_float4(p2.x, p2.y, p3.x, p3.y);
}

__device__ __forceinline__ unsigned short bf16bits(float v) {
    __nv_bfloat16 b = __float2bfloat16(v);
    unsigned short s; memcpy(&s, &b, 2); return s;
}
__device__ __forceinline__ float bf16val(float v) {
    return __bfloat162float(__float2bfloat16(v));
}

// ---------------- K1: x stats partials --------------------------------------
__global__ void __launch_bounds__(256)
k_xstats(const float* __restrict__ x) {
    __shared__ float smS[8 * 128], smQ[8 * 128];
    int t  = threadIdx.x;
    int c4 = t & 31;
    int rs = t >> 5;
    int r0 = blockIdx.x * 64;

    const float4* xg = (const float4*)x;
    float4 s = make_float4(0.f, 0.f, 0.f, 0.f);
    float4 q = make_float4(0.f, 0.f, 0.f, 0.f);
    #pragma unroll
    for (int r = rs; r < 64; r += 8) {
        float4 v = xg[(size_t)(r0 + r) * 32 + c4];
        s.x += v.x; s.y += v.y; s.z += v.z; s.w += v.w;
        q.x += v.x * v.x; q.y += v.y * v.y; q.z += v.z * v.z; q.w += v.w * v.w;
    }
    ((float4*)smS)[rs * 32 + c4] = s;
    ((float4*)smQ)[rs * 32 + c4] = q;
    __syncthreads();
    if (t < 128) {
        float ss = 0.f, qq = 0.f;
        #pragma unroll
        for (int j = 0; j < 8; j++) { ss += smS[j * 128 + t]; qq += smQ[j * 128 + t]; }
        g_xs_part[blockIdx.x * 128 + t] = ss;
        g_xq_part[blockIdx.x * 128 + t] = qq;
    }
}

// ---------------- K2: normalize x -> bf16 hi/lo; W -> bf16 hi/lo; h init ----
__global__ void __launch_bounds__(256)
k_xnorm(const float* __restrict__ x,
        const float* __restrict__ nq_w, const float* __restrict__ nq_b,
        const float* __restrict__ nq_ms,
        const float* __restrict__ wq, const float* __restrict__ wk,
        const float* __restrict__ wv) {
    int tid = threadIdx.x;
    int b   = blockIdx.x;

    if (b == 0 && tid < DH) { g_hsum[tid] = 0.f; g_hsumsq[tid] = 0.f; }

    uint2* xh = (uint2*)g_xhi;
    uint2* xl = (uint2*)g_xlo;
    uint2* wh = (uint2*)g_whi;
    uint2* wl = (uint2*)g_wlo;

    if (b < 48) {
        __shared__ float As[128], Bs[128];
        if (tid < 128) {
            float ss = 0.f, qq = 0.f;
            #pragma unroll 8
            for (int p = 0; p < 96; p++) {
                ss += g_xs_part[p * 128 + tid];
                qq += g_xq_part[p * 128 + tid];
            }
            const float invN = 1.0f / NN;
            float mean = ss * invN;
            float ex2  = qq * invN;
            float mm   = mean * nq_ms[tid];
            float var  = ex2 - 2.f * mm * mean + mm * mm;
            float rinv = rsqrtf(var + 1e-5f);
            As[tid] = nq_w[tid] * rinv;
            Bs[tid] = nq_b[tid] - nq_w[tid] * rinv * mm;
        }
        __syncthreads();
        int r0 = b * 128;
        const float4* xg = (const float4*)x;
        for (int i = tid; i < 128 * 32; i += 256) {
            int row = i >> 5, c4 = i & 31, c = c4 * 4;
            float4 v = xg[(size_t)(r0 + row) * 32 + c4];
            float f[4];
            f[0] = fmaf(v.x, As[c],     Bs[c]);
            f[1] = fmaf(v.y, As[c + 1], Bs[c + 1]);
            f[2] = fmaf(v.z, As[c + 2], Bs[c + 2]);
            f[3] = fmaf(v.w, As[c + 3], Bs[c + 3]);
            unsigned short h[4], l[4];
            #pragma unroll
            for (int j = 0; j < 4; j++) {
                h[j] = bf16bits(f[j]);
                l[j] = bf16bits(f[j] - bf16val(f[j]));
            }
            uint2 uh, ul;
            uh.x = (u32)h[0] | ((u32)h[1] << 16); uh.y = (u32)h[2] | ((u32)h[3] << 16);
            ul.x = (u32)l[0] | ((u32)l[1] << 16); ul.y = (u32)l[2] | ((u32)l[3] << 16);
            size_t idx = (size_t)(r0 + row) * 32 + c4;
            xh[idx] = uh; xl[idx] = ul;
        }
        // residual init: g_h = x[:, :64] + x[:, 64:]
        float4* h4 = (float4*)g_h;
        for (int i = tid; i < 128 * 16; i += 256) {
            int row = i >> 4, c4 = i & 15;
            float4 xa = xg[(size_t)(r0 + row) * 32 + c4];
            float4 xb = xg[(size_t)(r0 + row) * 32 + 16 + c4];
            h4[(size_t)(r0 + row) * 16 + c4] =
                make_float4(xa.x + xb.x, xa.y + xb.y, xa.z + xb.z, xa.w + xb.w);
        }
    } else {
        int wr0 = (b - 48) * 128;
        for (int i = tid; i < 128 * 32; i += 256) {
            int row = i >> 5, c4 = i & 31;
            int gidx = wr0 + row;
            int mat = gidx >> 9, lr = gidx & 511;
            const float4* src = (const float4*)(mat == 0 ? wq : (mat == 1 ? wk : wv));
            float4 v = src[(size_t)lr * 32 + c4];
            float f[4] = {v.x, v.y, v.z, v.w};
            unsigned short h[4], l[4];
            #pragma unroll
            for (int j = 0; j < 4; j++) {
                h[j] = bf16bits(f[j]);
                l[j] = bf16bits(f[j] - bf16val(f[j]));
            }
            uint2 uh, ul;
            uh.x = (u32)h[0] | ((u32)h[1] << 16); uh.y = (u32)h[2] | ((u32)h[3] << 16);
            ul.x = (u32)l[0] | ((u32)l[1] << 16); ul.y = (u32)l[2] | ((u32)l[3] << 16);
            size_t idx = (size_t)gidx * 32 + c4;
            wh[idx] = uh; wl[idx] = ul;
        }
    }
}

// ---------------- K3: QKV GEMM via mma.sync bf16 split (hi+lo) --------------
#define ROWB 272
#define ATILE (128 * ROWB)
#define BTILE (64 * ROWB)
__global__ void __launch_bounds__(256, 2)
k_qkv(const float* __restrict__ bq, const float* __restrict__ bk,
      const float* __restrict__ bv) {
    extern __shared__ char smc[];
    float* bias_s = (float*)smc;
    char* aH = smc + 512;
    char* aL = aH + ATILE;
    char* bH = aL + ATILE;
    char* bL = bH + BTILE;

    int tid = threadIdx.x;
    int m0 = blockIdx.x * 128;
    int oc = blockIdx.y * 64;
    int mat = oc >> 9, o0 = oc & 511;
    const float* bias = mat == 0 ? bq : (mat == 1 ? bk : bv);
    if (tid < 64) bias_s[tid] = bias[o0 + tid];

    const uint4* xh4 = (const uint4*)g_xhi;   // 16 uint4 per 128-ch row
    const uint4* xl4 = (const uint4*)g_xlo;
    const uint4* wh4 = (const uint4*)g_whi;
    const uint4* wl4 = (const uint4*)g_wlo;

    #pragma unroll
    for (int i = tid; i < 2048; i += 256) {
        int row = i >> 4, c8 = i & 15;
        int so = row * ROWB + c8 * 16;
        size_t ax = (size_t)(m0 + row) * 16 + c8;
        *(uint4*)(aH + so) = xh4[ax];
        *(uint4*)(aL + so) = xl4[ax];
    }
    #pragma unroll
    for (int i = tid; i < 1024; i += 256) {
        int row = i >> 4, c8 = i & 15;
        int so = row * ROWB + c8 * 16;
        size_t bx = (size_t)(oc + row) * 16 + c8;
        *(uint4*)(bH + so) = wh4[bx];
        *(uint4*)(bL + so) = wl4[bx];
    }
    __syncthreads();

    u32 sb = smem_u32(smc);
    u32 aHb = sb + 512, aLb = aHb + ATILE, bHb = aLb + ATILE, bLb = bHb + BTILE;

    int t   = tid & 31;
    int wid = tid >> 5;
    int wm = (wid & 3) * 32;
    int wn = (wid >> 2) * 32;
    int rowA = ((t >> 3) & 1) * 8 + (t & 7);
    int kofA = (t >> 4) * 8;
    int rowB = (t & 7);
    int kofB = ((t >> 3) & 1) * 8;

    float acc[2][4][4];
    #pragma unroll
    for (int mf = 0; mf < 2; mf++)
        #pragma unroll
        for (int nf = 0; nf < 4; nf++)
            #pragma unroll
            for (int j = 0; j < 4; j++) acc[mf][nf][j] = 0.f;

    for (int k = 0; k < 128; k += 16) {
        u32 ah[2][4], al[2][4], bh[4][2], bl[4][2];
        #pragma unroll
        for (int mf = 0; mf < 2; mf++) {
            u32 off = (u32)((wm + mf * 16 + rowA) * ROWB + (k + kofA) * 2);
            ldsm_x4(ah[mf][0], ah[mf][1], ah[mf][2], ah[mf][3], aHb + off);
            ldsm_x4(al[mf][0], al[mf][1], al[mf][2], al[mf][3], aLb + off);
        }
        #pragma unroll
        for (int nf = 0; nf < 4; nf++) {
            u32 off = (u32)((wn + nf * 8 + rowB) * ROWB + (k + kofB) * 2);
            ldsm_x2(bh[nf][0], bh[nf][1], bHb + off);
            ldsm_x2(bl[nf][0], bl[nf][1], bLb + off);
        }
        #pragma unroll
        for (int mf = 0; mf < 2; mf++)
            #pragma unroll
            for (int nf = 0; nf < 4; nf++) {
                mma_bf16(acc[mf][nf], ah[mf], bh[nf]);
                mma_bf16(acc[mf][nf], ah[mf], bl[nf]);
                mma_bf16(acc[mf][nf], al[mf], bh[nf]);
            }
    }

    int tq = t >> 2, tr = t & 3;
    #pragma unroll
    for (int mf = 0; mf < 2; mf++) {
        int m = m0 + wm + mf * 16 + tq;
        #pragma unroll
        for (int nf = 0; nf < 4; nf++) {
            int ln = wn + nf * 8 + tr * 2;
            float b0 = bias_s[ln], b1 = bias_s[ln + 1];
            *(__half2*)(g_qkv + (size_t)m * QKV_W + oc + ln) =
                __floats2half2_rn(acc[mf][nf][0] + b0, acc[mf][nf][1] + b1);
            *(__half2*)(g_qkv + (size_t)(m + 8) * QKV_W + oc + ln) =
                __floats2half2_rn(acc[mf][nf][2] + b0, acc[mf][nf][3] + b1);
        }
    }
}

// ---------------- K4: attention, 2 heads of one set per CTA (fp16 gmem) -----
// ROUND-13 VERSION (proven 18.4us): all-fp32 smem, one-shot converts in loader
#define PBUF 1192   // float4 units per head: q 408 | kt 400 | v 384
__global__ void __launch_bounds__(192, 5)
k_attn() {
    __shared__ float4 buf[2][PBUF];
    __shared__ __align__(16) float alphaT[2][24 * 24];   // [s][d]

    int tid = threadIdx.x;
    int set = blockIdx.x >> 2;
    int h0  = (blockIdx.x & 3) << 1;
    int n0  = set * G;

    const uint4* srcH = (const uint4*)g_qkv + (size_t)n0 * 192;  // 192 uint4/row
    #pragma unroll
    for (int p = 0; p < 2; p++) {
        int h = h0 + p;
        float4* q4h = buf[p];
        float4* kt4 = buf[p] + 408;
        float4* v4h = buf[p] + 808;
        int n = tid >> 3, g = tid & 7;           // 192 items exactly
        uint4 uq = srcH[n * 192 + h * 8 + g];
        uint4 uk = srcH[n * 192 + 64 + h * 8 + g];
        uint4 uv = srcH[n * 192 + 128 + h * 8 + g];
        float4 f0, f1;
        cvt8(uq, f0, f1);
        q4h[n * 17 + 2 * g] = f0; q4h[n * 17 + 2 * g + 1] = f1;
        cvt8(uk, f0, f1);
        kt4[(2 * g) * 25 + n] = f0; kt4[(2 * g + 1) * 25 + n] = f1;
        cvt8(uv, f0, f1);
        v4h[n * 16 + 2 * g] = f0; v4h[n * 16 + 2 * g + 1] = f1;
    }
    __syncthreads();

    // logits: 192 threads = 2 heads x 96 (each: 2 d x 3 s)
    {
        int p = tid >= 96;
        int r = tid - p * 96;
        const ulonglong2* q8 = (const ulonglong2*)buf[p];
        const ulonglong2* k8 = (const ulonglong2*)(buf[p] + 408);
        float* aT = alphaT[p];
        int d0 = (r >> 3) * 2;
        int sg = r & 7;
        u64 a00 = 0, a01 = 0, a02 = 0, a10 = 0, a11 = 0, a12 = 0;
        #pragma unroll
        for (int j = 0; j < 16; j++) {
            ulonglong2 q0 = q8[d0 * 17 + j];
            ulonglong2 q1 = q8[(d0 + 1) * 17 + j];
            ulonglong2 k0 = k8[j * 25 + sg * 3];
            ulonglong2 k1 = k8[j * 25 + sg * 3 + 1];
            ulonglong2 k2 = k8[j * 25 + sg * 3 + 2];
            a00 = fma2(q0.x, k0.x, a00); a00 = fma2(q0.y, k0.y, a00);
            a01 = fma2(q0.x, k1.x, a01); a01 = fma2(q0.y, k1.y, a01);
            a02 = fma2(q0.x, k2.x, a02); a02 = fma2(q0.y, k2.y, a02);
            a10 = fma2(q1.x, k0.x, a10); a10 = fma2(q1.y, k0.y, a10);
            a11 = fma2(q1.x, k1.x, a11); a11 = fma2(q1.y, k1.y, a11);
            a12 = fma2(q1.x, k2.x, a12); a12 = fma2(q1.y, k2.y, a12);
        }
        float lo, hi;
        int s0 = sg * 3;
        unpack2(a00, lo, hi); aT[(s0 + 0) * 24 + d0]     = (lo + hi) * 0.125f;
        unpack2(a01, lo, hi); aT[(s0 + 1) * 24 + d0]     = (lo + hi) * 0.125f;
        unpack2(a02, lo, hi); aT[(s0 + 2) * 24 + d0]     = (lo + hi) * 0.125f;
        unpack2(a10, lo, hi); aT[(s0 + 0) * 24 + d0 + 1] = (lo + hi) * 0.125f;
        unpack2(a11, lo, hi); aT[(s0 + 1) * 24 + d0 + 1] = (lo + hi) * 0.125f;
        unpack2(a12, lo, hi); aT[(s0 + 2) * 24 + d0 + 1] = (lo + hi) * 0.125f;
    }
    __syncthreads();

    // softmax: 48 threads = 2 heads x 24 destinations
    if (tid < 48) {
        int p = tid / 24, d = tid - p * 24;
        float* aT = alphaT[p];
        float m = aT[d];
        #pragma unroll
        for (int s = 1; s < G; s++) m = fmaxf(m, aT[s * 24 + d]);
        float sum = 0.f;
        #pragma unroll
        for (int s = 0; s < G; s++) {
            float e = expf(aT[s * 24 + d] - m);
            aT[s * 24 + d] = e;
            sum += e;
        }
        float inv = 1.0f / (sum + 1e-16f);
        #pragma unroll
        for (int s = 0; s < G; s++) aT[s * 24 + d] *= inv;
    }
    __syncthreads();

    // aggregate: 96 threads (dg, c4); both heads summed into the same accs
    if (tid < 96) {
        int dg = tid >> 4, c4 = tid & 15, d0 = dg * 4;
        u64 acc[4][2];
        #pragma unroll
        for (int i2 = 0; i2 < 4; i2++) { acc[i2][0] = 0ull; acc[i2][1] = 0ull; }
        #pragma unroll
        for (int p = 0; p < 2; p++) {
            const ulonglong2* v8 = (const ulonglong2*)(buf[p] + 808);
            const float* aT = alphaT[p];
            #pragma unroll
            for (int s = 0; s < G; s++) {
                float4 al = *(const float4*)&aT[s * 24 + d0];
                ulonglong2 vv = v8[s * 16 + c4];
                u64 pp;
                pp = pack2(al.x, al.x); acc[0][0] = fma2(pp, vv.x, acc[0][0]); acc[0][1] = fma2(pp, vv.y, acc[0][1]);
                pp = pack2(al.y, al.y); acc[1][0] = fma2(pp, vv.x, acc[1][0]); acc[1][1] = fma2(pp, vv.y, acc[1][1]);
                pp = pack2(al.z, al.z); acc[2][0] = fma2(pp, vv.x, acc[2][0]); acc[2][1] = fma2(pp, vv.y, acc[2][1]);
                pp = pack2(al.w, al.w); acc[3][0] = fma2(pp, vv.x, acc[3][0]); acc[3][1] = fma2(pp, vv.y, acc[3][1]);
            }
        }
        #pragma unroll
        for (int i2 = 0; i2 < 4; i2++) {
            float* dst = g_h + (size_t)(n0 + d0 + i2) * DH + c4 * 4;
            float x0, x1, x2, x3;
            unpack2(acc[i2][0], x0, x1);
            unpack2(acc[i2][1], x2, x3);
            atomicAdd(dst + 0, x0 * 0.125f);
            atomicAdd(dst + 1, x1 * 0.125f);
            atomicAdd(dst + 2, x2 * 0.125f);
            atomicAdd(dst + 3, x3 * 0.125f);
        }
    }
}

// ---------------- K5: h stats (96 blocks x 64 rows) -------------------------
__global__ void __launch_bounds__(256)
k_hstats() {
    __shared__ float smS[16 * 64], smQ[16 * 64];
    int t  = threadIdx.x;
    int c4 = t & 15;
    int rs = t >> 4;
    int r0 = blockIdx.x * 64;

    const float4* h4 = (const float4*)g_h;
    float4 s = make_float4(0.f, 0.f, 0.f, 0.f);
    float4 q = make_float4(0.f, 0.f, 0.f, 0.f);
    #pragma unroll
    for (int r = rs; r < 64; r += 16) {
        float4 a = h4[(size_t)(r0 + r) * 16 + c4];
        s.x += a.x; s.y += a.y; s.z += a.z; s.w += a.w;
        q.x += a.x * a.x; q.y += a.y * a.y; q.z += a.z * a.z; q.w += a.w * a.w;
    }
    ((float4*)smS)[rs * 16 + c4] = s;
    ((float4*)smQ)[rs * 16 + c4] = q;
    __syncthreads();
    if (t < 64) {
        float ss = 0.f, qq = 0.f;
        #pragma unroll
        for (int j = 0; j < 16; j++) { ss += smS[j * 64 + t]; qq += smQ[j * 64 + t]; }
        atomicAdd(&g_hsum[t], ss);
        atomicAdd(&g_hsumsq[t], qq);
    }
}

__device__ __forceinline__ float gelu_exact(float v) {
    return 0.5f * v * (1.0f + erff(v * 0.70710678118654752f));
}

// ---------------- K6: global norm + PFF + per-set norm + score + pooling ----
#define WPU 65
__global__ void __launch_bounds__(256)
k_final(const float* __restrict__ x,
        const float* __restrict__ no_w, const float* __restrict__ no_b,
        const float* __restrict__ no_ms,
        const float* __restrict__ o_w1, const float* __restrict__ o_b1,
        const float* __restrict__ o_w2, const float* __restrict__ o_b2,
        const float* __restrict__ pn_w, const float* __restrict__ pn_b,
        const float* __restrict__ pn_ms,
        const float* __restrict__ p_w1, const float* __restrict__ p_b1,
        const float* __restrict__ p_w2, const float* __restrict__ p_b2,
        float* __restrict__ out) {
    extern __shared__ float dsm[];
    u64*  w1P  = (u64*)dsm;
    u64*  w2P  = w1P + 32 * WPU;
    u64*  pw1P = w2P + 32 * WPU;
    u64*  pw2P = pw1P + 32 * WPU;
    float* hs  = (float*)(pw2P + 32);
    float* hn  = hs + G * DH;
    float* t1  = hn + G * DH;
    float* h2  = t1 + G * DH;
    float* a2  = h2 + G * DH;
    float* b2v = a2 + DH;
    float* cm  = b2v + DH;
    float* cr  = cm + DH;
    float* b1s = cr + DH;
    float* b2s = b1s + DH;
    float* pb1s = b2s + DH;
    float* score = pb1s + DH;
    float* wsf   = score + G;

    int tid = threadIdx.x;
    int n0  = blockIdx.x * G;

    for (int i = tid; i < 64 * 32; i += 256) {
        int j = i >> 5, c2 = i & 31;
        float2 w1v = *(const float2*)(o_w1 + j * 64 + c2 * 2);
        w1P[c2 * WPU + j] = pack2(w1v.x, w1v.y);
        float2 pw = *(const float2*)(p_w1 + j * 64 + c2 * 2);
        pw1P[c2 * WPU + j] = pack2(pw.x, pw.y);
        float2 w2v = *(const float2*)(o_w2 + j * 64 + c2 * 2);
        w2P[c2 * WPU + j] = pack2(w2v.x, w2v.y);
    }
    if (tid < 32) {
        pw2P[tid] = pack2(p_w2[tid * 2], p_w2[tid * 2 + 1]);
    }
    if (tid < DH) {
        b1s[tid] = o_b1[tid]; b2s[tid] = o_b2[tid];
        pb1s[tid] = p_b1[tid];
        const float invN = 1.0f / NN;
        float mean = g_hsum[tid] * invN;
        float ex2  = g_hsumsq[tid] * invN;
        float mm   = mean * no_ms[tid];
        float var  = ex2 - 2.f * mm * mean + mm * mm;
        float rinv = rsqrtf(var + 1e-5f);
        a2[tid] = no_w[tid] * rinv;
        b2v[tid] = no_b[tid] - no_w[tid] * rinv * mm;
    }
    for (int i = tid; i < G * DH; i += 256) hs[i] = g_h[(size_t)n0 * DH + i];
    __syncthreads();

    for (int i = tid; i < G * DH; i += 256) {
        int c = i & 63;
        hn[i] = fmaf(hs[i], a2[c], b2v[c]);
    }
    __syncthreads();

    for (int i = tid; i < 384; i += 256) {
        int dp = i >> 5, jp = i & 31, d0 = dp * 2;
        u64 A00 = 0, A01 = 0, A10 = 0, A11 = 0;
        const u64* h0 = (const u64*)(hn + d0 * DH);
        const u64* h1 = (const u64*)(hn + (d0 + 1) * DH);
        #pragma unroll 8
        for (int c2 = 0; c2 < 32; c2++) {
            u64 w0 = w1P[c2 * WPU + jp], w1 = w1P[c2 * WPU + jp + 32];
            u64 hc0 = h0[c2], hc1 = h1[c2];
            A00 = fma2(hc0, w0, A00); A01 = fma2(hc0, w1, A01);
            A10 = fma2(hc1, w0, A10); A11 = fma2(hc1, w1, A11);
        }
        float lo, hi;
        unpack2(A00, lo, hi); t1[d0 * DH + jp]            = gelu_exact(lo + hi + b1s[jp]);
        unpack2(A01, lo, hi); t1[d0 * DH + jp + 32]       = gelu_exact(lo + hi + b1s[jp + 32]);
        unpack2(A10, lo, hi); t1[(d0 + 1) * DH + jp]      = gelu_exact(lo + hi + b1s[jp]);
        unpack2(A11, lo, hi); t1[(d0 + 1) * DH + jp + 32] = gelu_exact(lo + hi + b1s[jp + 32]);
    }
    __syncthreads();

    for (int i = tid; i < 384; i += 256) {
        int dp = i >> 5, cp = i & 31, d0 = dp * 2;
        u64 A00 = 0, A01 = 0, A10 = 0, A11 = 0;
        const u64* t0 = (const u64*)(t1 + d0 * DH);
        const u64* t1r = (const u64*)(t1 + (d0 + 1) * DH);
        #pragma unroll 8
        for (int j2 = 0; j2 < 32; j2++) {
            u64 w0 = w2P[j2 * WPU + cp], w1 = w2P[j2 * WPU + cp + 32];
            u64 tc0 = t0[j2], tc1 = t1r[j2];
            A00 = fma2(tc0, w0, A00); A01 = fma2(tc0, w1, A01);
            A10 = fma2(tc1, w0, A10); A11 = fma2(tc1, w1, A11);
        }
        float lo, hi;
        unpack2(A00, lo, hi); h2[d0 * DH + cp]            = hs[d0 * DH + cp] + lo + hi + b2s[cp];
        unpack2(A01, lo, hi); h2[d0 * DH + cp + 32]       = hs[d0 * DH + cp + 32] + lo + hi + b2s[cp + 32];
        unpack2(A10, lo, hi); h2[(d0 + 1) * DH + cp]      = hs[(d0 + 1) * DH + cp] + lo + hi + b2s[cp];
        unpack2(A11, lo, hi); h2[(d0 + 1) * DH + cp + 32] = hs[(d0 + 1) * DH + cp + 32] + lo + hi + b2s[cp + 32];
    }
    __syncthreads();

    if (tid < DH) {
        int c = tid;
        float m = 0.f;
        #pragma unroll
        for (int d = 0; d < G; d++) m += h2[d * DH + c];
        m *= (1.0f / G);
        float mm = m * pn_ms[c];
        float vv = 0.f;
        #pragma unroll
        for (int d = 0; d < G; d++) { float t = h2[d * DH + c] - mm; vv += t * t; }
        vv *= (1.0f / G);
        cm[c] = mm;
        cr[c] = pn_w[c] * rsqrtf(vv + 1e-5f);
    }
    __syncthreads();

    for (int i = tid; i < G * DH; i += 256) {
        int c = i & 63;
        hn[i] = fmaf(h2[i] - cm[c], cr[c], pn_b[c]);
    }
    __syncthreads();

    for (int i = tid; i < 384; i += 256) {
        int dp = i >> 5, jp = i & 31, d0 = dp * 2;
        u64 A00 = 0, A01 = 0, A10 = 0, A11 = 0;
        const u64* h0 = (const u64*)(hn + d0 * DH);
        const u64* h1 = (const u64*)(hn + (d0 + 1) * DH);
        #pragma unroll 8
        for (int c2 = 0; c2 < 32; c2++) {
            u64 w0 = pw1P[c2 * WPU + jp], w1 = pw1P[c2 * WPU + jp + 32];
            u64 hc0 = h0[c2], hc1 = h1[c2];
            A00 = fma2(hc0, w0, A00); A01 = fma2(hc0, w1, A01);
            A10 = fma2(hc1, w0, A10); A11 = fma2(hc1, w1, A11);
        }
        float lo, hi;
        unpack2(A00, lo, hi); t1[d0 * DH + jp]            = gelu_exact(lo + hi + pb1s[jp]);
        unpack2(A01, lo, hi); t1[d0 * DH + jp + 32]       = gelu_exact(lo + hi + pb1s[jp + 32]);
        unpack2(A10, lo, hi); t1[(d0 + 1) * DH + jp]      = gelu_exact(lo + hi + pb1s[jp]);
        unpack2(A11, lo, hi); t1[(d0 + 1) * DH + jp + 32] = gelu_exact(lo + hi + pb1s[jp + 32]);
    }
    __syncthreads();

    if (tid < G) {
        const u64* tr = (const u64*)(t1 + tid * DH);
        u64 A = 0;
        #pragma unroll 8
        for (int j2 = 0; j2 < 32; j2++) A = fma2(tr[j2], pw2P[j2], A);
        float lo, hi;
        unpack2(A, lo, hi);
        score[tid] = lo + hi + p_b2[0];
    }
    __syncthreads();

    if (tid == 0) {
        float m = score[0];
        #pragma unroll
        for (int d = 1; d < G; d++) m = fmaxf(m, score[d]);
        float sum = 0.f;
        #pragma unroll
        for (int d = 0; d < G; d++) { wsf[d] = expf(score[d] - m); sum += wsf[d]; }
        float inv = 1.0f / (sum + 1e-16f);
        #pragma unroll
        for (int d = 0; d < G; d++) wsf[d] *= inv;
    }
    __syncthreads();

    if (tid < DIN) {
        float acc = 0.f;
        #pragma unroll
        for (int d = 0; d < G; d++)
            acc = fmaf(wsf[d], x[(size_t)(n0 + d) * DIN + tid], acc);
        out[blockIdx.x * DIN + tid] = acc;
    }
}

// ---------------- launch -----------------------------------------------------
extern "C" void kernel_launch(void* const* d_in, const int* in_sizes, int n_in,
                              void* d_out, int out_size) {
    const float* x     = (const float*)d_in[0];
    const float* nq_w  = (const float*)d_in[4];
    const float* nq_b  = (const float*)d_in[5];
    const float* nq_ms = (const float*)d_in[6];
    const float* wq    = (const float*)d_in[7];
    const float* bq    = (const float*)d_in[8];
    const float* wk    = (const float*)d_in[9];
    const float* bk    = (const float*)d_in[10];
    const float* wv    = (const float*)d_in[11];
    const float* bv    = (const float*)d_in[12];
    const float* no_w  = (const float*)d_in[13];
    const float* no_b  = (const float*)d_in[14];
    const float* no_ms = (const float*)d_in[15];
    const float* o_w1  = (const float*)d_in[16];
    const float* o_b1  = (const float*)d_in[17];
    const float* o_w2  = (const float*)d_in[18];
    const float* o_b2  = (const float*)d_in[19];
    const float* pn_w  = (const float*)d_in[20];
    const float* pn_b  = (const float*)d_in[21];
    const float* pn_ms = (const float*)d_in[22];
    const float* p_w1  = (const float*)d_in[23];
    const float* p_b1  = (const float*)d_in[24];
    const float* p_w2  = (const float*)d_in[25];
    const float* p_b2  = (const float*)d_in[26];
    float* out = (float*)d_out;

    const int smem_qkv = 512 + 2 * ATILE + 2 * BTILE;
    const int smem_fin = (3 * 32 * WPU + 32) * 8 + (4 * G * DH + 7 * DH + 2 * G) * 4;
    cudaFuncSetAttribute(k_qkv,   cudaFuncAttributeMaxDynamicSharedMemorySize, smem_qkv);
    cudaFuncSetAttribute(k_final, cudaFuncAttributeMaxDynamicSharedMemorySize, smem_fin);

    k_xstats<<<96, 256>>>(x);
    k_xnorm<<<60, 256>>>(x, nq_w, nq_b, nq_ms, wq, wk, wv);
    k_qkv<<<dim3(48, 24), 256, smem_qkv>>>(bq, bk, bv);
    k_attn<<<1024, 192>>>();
    k_hstats<<<96, 256>>>();
    k_final<<<256, 256, smem_fin>>>(x, no_w, no_b, no_ms,
                                    o_w1, o_b1, o_w2, o_b2,
                                    pn_w, pn_b, pn_ms,
                                    p_w1, p_b1, p_w2, p_b2, out);
}

// round 16
// speedup vs baseline: 1.0557x; 1.0084x over previous
#include <cuda_runtime.h>
#include <cuda_bf16.h>
#include <cuda_fp16.h>
#include <math.h>
#include <string.h>

#define NN   6144
#define G    24
#define DIN  128
#define DH   64
#define NH   8
#define QKV_W 1536

typedef unsigned long long u64;
typedef unsigned int u32;

// ---------------- device scratch --------------------------------------------
__device__ __half g_qkv[NN * QKV_W];           // 18.9 MB fp16 qkv
__device__ float g_h[NN * DH];
__device__ unsigned short g_xhi[NN * DIN];
__device__ unsigned short g_xlo[NN * DIN];
__device__ unsigned short g_whi[QKV_W * DIN];
__device__ unsigned short g_wlo[QKV_W * DIN];
__device__ float g_xs_part[96 * DIN];
__device__ float g_xq_part[96 * DIN];
__device__ float g_hsum[DH];
__device__ float g_hsumsq[DH];

// ---------------- PTX helpers -----------------------------------------------
__device__ __forceinline__ u32 smem_u32(const void* p) {
    u32 a;
    asm("{ .reg .u64 t; cvta.to.shared.u64 t, %1; cvt.u32.u64 %0, t; }"
        : "=r"(a) : "l"(p));
    return a;
}
__device__ __forceinline__ void ldsm_x4(u32& r0, u32& r1, u32& r2, u32& r3, u32 addr) {
    asm volatile("ldmatrix.sync.aligned.m8n8.x4.shared.b16 {%0,%1,%2,%3}, [%4];"
                 : "=r"(r0), "=r"(r1), "=r"(r2), "=r"(r3) : "r"(addr));
}
__device__ __forceinline__ void ldsm_x2(u32& r0, u32& r1, u32 addr) {
    asm volatile("ldmatrix.sync.aligned.m8n8.x2.shared.b16 {%0,%1}, [%2];"
                 : "=r"(r0), "=r"(r1) : "r"(addr));
}
__device__ __forceinline__ void mma_bf16(float* d, const u32* a, const u32* b) {
    asm volatile(
        "mma.sync.aligned.m16n8k16.row.col.f32.bf16.bf16.f32 "
        "{%0,%1,%2,%3},{%4,%5,%6,%7},{%8,%9},{%0,%1,%2,%3};"
        : "+f"(d[0]), "+f"(d[1]), "+f"(d[2]), "+f"(d[3])
        : "r"(a[0]), "r"(a[1]), "r"(a[2]), "r"(a[3]), "r"(b[0]), "r"(b[1]));
}
__device__ __forceinline__ u64 pack2(float lo, float hi) {
    u64 r; asm("mov.b64 %0,{%1,%2};" : "=l"(r) : "f"(lo), "f"(hi)); return r;
}
__device__ __forceinline__ u64 fma2(u64 a, u64 b, u64 c) {
    u64 d; asm("fma.rn.f32x2 %0,%1,%2,%3;" : "=l"(d) : "l"(a), "l"(b), "l"(c)); return d;
}
__device__ __forceinline__ void unpack2(u64 v, float& lo, float& hi) {
    asm("mov.b64 {%0,%1},%2;" : "=f"(lo), "=f"(hi) : "l"(v));
}
__device__ __forceinline__ void cvt8(uint4 u, float4& a, float4& b) {
    float2 p0 = __half22float2(*(__half2*)&u.x);
    float2 p1 = __half22float2(*(__half2*)&u.y);
    float2 p2 = __half22float2(*(__half2*)&u.z);
    float2 p3 = __half22float2(*(__half2*)&u.w);
    a = make_float4(p0.x, p0.y, p1.x, p1.y);
    b = make_float4(p2.x, p2.y, p3.x, p3.y);
}

__device__ __forceinline__ unsigned short bf16bits(float v) {
    __nv_bfloat16 b = __float2bfloat16(v);
    unsigned short s; memcpy(&s, &b, 2); return s;
}
__device__ __forceinline__ float bf16val(float v) {
    return __bfloat162float(__float2bfloat16(v));
}

// ---------------- K1: x stats partials --------------------------------------
__global__ void __launch_bounds__(256)
k_xstats(const float* __restrict__ x) {
    __shared__ float smS[8 * 128], smQ[8 * 128];
    int t  = threadIdx.x;
    int c4 = t & 31;
    int rs = t >> 5;
    int r0 = blockIdx.x * 64;

    const float4* xg = (const float4*)x;
    float4 s = make_float4(0.f, 0.f, 0.f, 0.f);
    float4 q = make_float4(0.f, 0.f, 0.f, 0.f);
    #pragma unroll
    for (int r = rs; r < 64; r += 8) {
        float4 v = xg[(size_t)(r0 + r) * 32 + c4];
        s.x += v.x; s.y += v.y; s.z += v.z; s.w += v.w;
        q.x += v.x * v.x; q.y += v.y * v.y; q.z += v.z * v.z; q.w += v.w * v.w;
    }
    ((float4*)smS)[rs * 32 + c4] = s;
    ((float4*)smQ)[rs * 32 + c4] = q;
    __syncthreads();
    if (t < 128) {
        float ss = 0.f, qq = 0.f;
        #pragma unroll
        for (int j = 0; j < 8; j++) { ss += smS[j * 128 + t]; qq += smQ[j * 128 + t]; }
        g_xs_part[blockIdx.x * 128 + t] = ss;
        g_xq_part[blockIdx.x * 128 + t] = qq;
    }
}

// ---------------- K2: normalize x -> bf16 hi/lo; W -> bf16 hi/lo; h init ----
__global__ void __launch_bounds__(256)
k_xnorm(const float* __restrict__ x,
        const float* __restrict__ nq_w, const float* __restrict__ nq_b,
        const float* __restrict__ nq_ms,
        const float* __restrict__ wq, const float* __restrict__ wk,
        const float* __restrict__ wv) {
    int tid = threadIdx.x;
    int b   = blockIdx.x;

    if (b == 0 && tid < DH) { g_hsum[tid] = 0.f; g_hsumsq[tid] = 0.f; }

    uint2* xh = (uint2*)g_xhi;
    uint2* xl = (uint2*)g_xlo;
    uint2* wh = (uint2*)g_whi;
    uint2* wl = (uint2*)g_wlo;

    if (b < 48) {
        __shared__ float As[128], Bs[128];
        if (tid < 128) {
            float ss = 0.f, qq = 0.f;
            #pragma unroll 8
            for (int p = 0; p < 96; p++) {
                ss += g_xs_part[p * 128 + tid];
                qq += g_xq_part[p * 128 + tid];
            }
            const float invN = 1.0f / NN;
            float mean = ss * invN;
            float ex2  = qq * invN;
            float mm   = mean * nq_ms[tid];
            float var  = ex2 - 2.f * mm * mean + mm * mm;
            float rinv = rsqrtf(var + 1e-5f);
            As[tid] = nq_w[tid] * rinv;
            Bs[tid] = nq_b[tid] - nq_w[tid] * rinv * mm;
        }
        __syncthreads();
        int r0 = b * 128;
        const float4* xg = (const float4*)x;
        for (int i = tid; i < 128 * 32; i += 256) {
            int row = i >> 5, c4 = i & 31, c = c4 * 4;
            float4 v = xg[(size_t)(r0 + row) * 32 + c4];
            float f[4];
            f[0] = fmaf(v.x, As[c],     Bs[c]);
            f[1] = fmaf(v.y, As[c + 1], Bs[c + 1]);
            f[2] = fmaf(v.z, As[c + 2], Bs[c + 2]);
            f[3] = fmaf(v.w, As[c + 3], Bs[c + 3]);
            unsigned short h[4], l[4];
            #pragma unroll
            for (int j = 0; j < 4; j++) {
                h[j] = bf16bits(f[j]);
                l[j] = bf16bits(f[j] - bf16val(f[j]));
            }
            uint2 uh, ul;
            uh.x = (u32)h[0] | ((u32)h[1] << 16); uh.y = (u32)h[2] | ((u32)h[3] << 16);
            ul.x = (u32)l[0] | ((u32)l[1] << 16); ul.y = (u32)l[2] | ((u32)l[3] << 16);
            size_t idx = (size_t)(r0 + row) * 32 + c4;
            xh[idx] = uh; xl[idx] = ul;
        }
        // residual init: g_h = x[:, :64] + x[:, 64:]
        float4* h4 = (float4*)g_h;
        for (int i = tid; i < 128 * 16; i += 256) {
            int row = i >> 4, c4 = i & 15;
            float4 xa = xg[(size_t)(r0 + row) * 32 + c4];
            float4 xb = xg[(size_t)(r0 + row) * 32 + 16 + c4];
            h4[(size_t)(r0 + row) * 16 + c4] =
                make_float4(xa.x + xb.x, xa.y + xb.y, xa.z + xb.z, xa.w + xb.w);
        }
    } else {
        int wr0 = (b - 48) * 128;
        for (int i = tid; i < 128 * 32; i += 256) {
            int row = i >> 5, c4 = i & 31;
            int gidx = wr0 + row;
            int mat = gidx >> 9, lr = gidx & 511;
            const float4* src = (const float4*)(mat == 0 ? wq : (mat == 1 ? wk : wv));
            float4 v = src[(size_t)lr * 32 + c4];
            float f[4] = {v.x, v.y, v.z, v.w};
            unsigned short h[4], l[4];
            #pragma unroll
            for (int j = 0; j < 4; j++) {
                h[j] = bf16bits(f[j]);
                l[j] = bf16bits(f[j] - bf16val(f[j]));
            }
            uint2 uh, ul;
            uh.x = (u32)h[0] | ((u32)h[1] << 16); uh.y = (u32)h[2] | ((u32)h[3] << 16);
            ul.x = (u32)l[0] | ((u32)l[1] << 16); ul.y = (u32)l[2] | ((u32)l[3] << 16);
            size_t idx = (size_t)gidx * 32 + c4;
            wh[idx] = uh; wl[idx] = ul;
        }
    }
}

// ---------------- K3: QKV GEMM via mma.sync bf16 split (hi+lo) --------------
// round-13 version (uint2 staging loads)
#define ROWB 272
#define ATILE (128 * ROWB)
#define BTILE (64 * ROWB)
__global__ void __launch_bounds__(256, 2)
k_qkv(const float* __restrict__ bq, const float* __restrict__ bk,
      const float* __restrict__ bv) {
    extern __shared__ char smc[];
    float* bias_s = (float*)smc;
    char* aH = smc + 512;
    char* aL = aH + ATILE;
    char* bH = aL + ATILE;
    char* bL = bH + BTILE;

    int tid = threadIdx.x;
    int m0 = blockIdx.x * 128;
    int oc = blockIdx.y * 64;
    int mat = oc >> 9, o0 = oc & 511;
    const float* bias = mat == 0 ? bq : (mat == 1 ? bk : bv);
    if (tid < 64) bias_s[tid] = bias[o0 + tid];

    const uint2* xh = (const uint2*)g_xhi;
    const uint2* xl = (const uint2*)g_xlo;
    const uint2* wh = (const uint2*)g_whi;
    const uint2* wl = (const uint2*)g_wlo;

    #pragma unroll
    for (int i = tid; i < 4096; i += 256) {
        int row = i >> 5, c4 = i & 31;
        int so = row * ROWB + c4 * 8;
        size_t ax = (size_t)(m0 + row) * 32 + c4;
        *(uint2*)(aH + so) = xh[ax];
        *(uint2*)(aL + so) = xl[ax];
    }
    #pragma unroll
    for (int i = tid; i < 2048; i += 256) {
        int row = i >> 5, c4 = i & 31;
        int so = row * ROWB + c4 * 8;
        size_t bx = (size_t)(oc + row) * 32 + c4;
        *(uint2*)(bH + so) = wh[bx];
        *(uint2*)(bL + so) = wl[bx];
    }
    __syncthreads();

    u32 sb = smem_u32(smc);
    u32 aHb = sb + 512, aLb = aHb + ATILE, bHb = aLb + ATILE, bLb = bHb + BTILE;

    int t   = tid & 31;
    int wid = tid >> 5;
    int wm = (wid & 3) * 32;
    int wn = (wid >> 2) * 32;
    int rowA = ((t >> 3) & 1) * 8 + (t & 7);
    int kofA = (t >> 4) * 8;
    int rowB = (t & 7);
    int kofB = ((t >> 3) & 1) * 8;

    float acc[2][4][4];
    #pragma unroll
    for (int mf = 0; mf < 2; mf++)
        #pragma unroll
        for (int nf = 0; nf < 4; nf++)
            #pragma unroll
            for (int j = 0; j < 4; j++) acc[mf][nf][j] = 0.f;

    for (int k = 0; k < 128; k += 16) {
        u32 ah[2][4], al[2][4], bh[4][2], bl[4][2];
        #pragma unroll
        for (int mf = 0; mf < 2; mf++) {
            u32 off = (u32)((wm + mf * 16 + rowA) * ROWB + (k + kofA) * 2);
            ldsm_x4(ah[mf][0], ah[mf][1], ah[mf][2], ah[mf][3], aHb + off);
            ldsm_x4(al[mf][0], al[mf][1], al[mf][2], al[mf][3], aLb + off);
        }
        #pragma unroll
        for (int nf = 0; nf < 4; nf++) {
            u32 off = (u32)((wn + nf * 8 + rowB) * ROWB + (k + kofB) * 2);
            ldsm_x2(bh[nf][0], bh[nf][1], bHb + off);
            ldsm_x2(bl[nf][0], bl[nf][1], bLb + off);
        }
        #pragma unroll
        for (int mf = 0; mf < 2; mf++)
            #pragma unroll
            for (int nf = 0; nf < 4; nf++) {
                mma_bf16(acc[mf][nf], ah[mf], bh[nf]);
                mma_bf16(acc[mf][nf], ah[mf], bl[nf]);
                mma_bf16(acc[mf][nf], al[mf], bh[nf]);
            }
    }

    int tq = t >> 2, tr = t & 3;
    #pragma unroll
    for (int mf = 0; mf < 2; mf++) {
        int m = m0 + wm + mf * 16 + tq;
        #pragma unroll
        for (int nf = 0; nf < 4; nf++) {
            int ln = wn + nf * 8 + tr * 2;
            float b0 = bias_s[ln], b1 = bias_s[ln + 1];
            *(__half2*)(g_qkv + (size_t)m * QKV_W + oc + ln) =
                __floats2half2_rn(acc[mf][nf][0] + b0, acc[mf][nf][1] + b1);
            *(__half2*)(g_qkv + (size_t)(m + 8) * QKV_W + oc + ln) =
                __floats2half2_rn(acc[mf][nf][2] + b0, acc[mf][nf][3] + b1);
        }
    }
}

// ---------------- K4: attention, 2 heads of one set per CTA (fp16 gmem) -----
// round-13 structure; loader batches all 6 LDG.128 before converts (MLP=6)
#define PBUF 1192   // float4 units per head: q 408 | kt 400 | v 384
__global__ void __launch_bounds__(192, 5)
k_attn() {
    __shared__ float4 buf[2][PBUF];
    __shared__ __align__(16) float alphaT[2][24 * 24];   // [s][d]

    int tid = threadIdx.x;
    int set = blockIdx.x >> 2;
    int h0  = (blockIdx.x & 3) << 1;
    int n0  = set * G;

    const uint4* srcH = (const uint4*)g_qkv + (size_t)n0 * 192;  // 192 uint4/row
    {
        int n = tid >> 3, g = tid & 7;           // 192 items exactly
        // front-batch all 6 global loads (both heads) before any convert
        uint4 u[2][3];
        #pragma unroll
        for (int p = 0; p < 2; p++) {
            int h = h0 + p;
            u[p][0] = srcH[n * 192 + h * 8 + g];
            u[p][1] = srcH[n * 192 + 64 + h * 8 + g];
            u[p][2] = srcH[n * 192 + 128 + h * 8 + g];
        }
        #pragma unroll
        for (int p = 0; p < 2; p++) {
            float4* q4h = buf[p];
            float4* kt4 = buf[p] + 408;
            float4* v4h = buf[p] + 808;
            float4 f0, f1;
            cvt8(u[p][0], f0, f1);
            q4h[n * 17 + 2 * g] = f0; q4h[n * 17 + 2 * g + 1] = f1;
            cvt8(u[p][1], f0, f1);
            kt4[(2 * g) * 25 + n] = f0; kt4[(2 * g + 1) * 25 + n] = f1;
            cvt8(u[p][2], f0, f1);
            v4h[n * 16 + 2 * g] = f0; v4h[n * 16 + 2 * g + 1] = f1;
        }
    }
    __syncthreads();

    // logits: 192 threads = 2 heads x 96 (each: 2 d x 3 s)
    {
        int p = tid >= 96;
        int r = tid - p * 96;
        const ulonglong2* q8 = (const ulonglong2*)buf[p];
        const ulonglong2* k8 = (const ulonglong2*)(buf[p] + 408);
        float* aT = alphaT[p];
        int d0 = (r >> 3) * 2;
        int sg = r & 7;
        u64 a00 = 0, a01 = 0, a02 = 0, a10 = 0, a11 = 0, a12 = 0;
        #pragma unroll
        for (int j = 0; j < 16; j++) {
            ulonglong2 q0 = q8[d0 * 17 + j];
            ulonglong2 q1 = q8[(d0 + 1) * 17 + j];
            ulonglong2 k0 = k8[j * 25 + sg * 3];
            ulonglong2 k1 = k8[j * 25 + sg * 3 + 1];
            ulonglong2 k2 = k8[j * 25 + sg * 3 + 2];
            a00 = fma2(q0.x, k0.x, a00); a00 = fma2(q0.y, k0.y, a00);
            a01 = fma2(q0.x, k1.x, a01); a01 = fma2(q0.y, k1.y, a01);
            a02 = fma2(q0.x, k2.x, a02); a02 = fma2(q0.y, k2.y, a02);
            a10 = fma2(q1.x, k0.x, a10); a10 = fma2(q1.y, k0.y, a10);
            a11 = fma2(q1.x, k1.x, a11); a11 = fma2(q1.y, k1.y, a11);
            a12 = fma2(q1.x, k2.x, a12); a12 = fma2(q1.y, k2.y, a12);
        }
        float lo, hi;
        int s0 = sg * 3;
        unpack2(a00, lo, hi); aT[(s0 + 0) * 24 + d0]     = (lo + hi) * 0.125f;
        unpack2(a01, lo, hi); aT[(s0 + 1) * 24 + d0]     = (lo + hi) * 0.125f;
        unpack2(a02, lo, hi); aT[(s0 + 2) * 24 + d0]     = (lo + hi) * 0.125f;
        unpack2(a10, lo, hi); aT[(s0 + 0) * 24 + d0 + 1] = (lo + hi) * 0.125f;
        unpack2(a11, lo, hi); aT[(s0 + 1) * 24 + d0 + 1] = (lo + hi) * 0.125f;
        unpack2(a12, lo, hi); aT[(s0 + 2) * 24 + d0 + 1] = (lo + hi) * 0.125f;
    }
    __syncthreads();

    // softmax: 48 threads = 2 heads x 24 destinations
    if (tid < 48) {
        int p = tid / 24, d = tid - p * 24;
        float* aT = alphaT[p];
        float m = aT[d];
        #pragma unroll
        for (int s = 1; s < G; s++) m = fmaxf(m, aT[s * 24 + d]);
        float sum = 0.f;
        #pragma unroll
        for (int s = 0; s < G; s++) {
            float e = expf(aT[s * 24 + d] - m);
            aT[s * 24 + d] = e;
            sum += e;
        }
        float inv = 1.0f / (sum + 1e-16f);
        #pragma unroll
        for (int s = 0; s < G; s++) aT[s * 24 + d] *= inv;
    }
    __syncthreads();

    // aggregate: 96 threads (dg, c4); both heads summed into the same accs
    if (tid < 96) {
        int dg = tid >> 4, c4 = tid & 15, d0 = dg * 4;
        u64 acc[4][2];
        #pragma unroll
        for (int i2 = 0; i2 < 4; i2++) { acc[i2][0] = 0ull; acc[i2][1] = 0ull; }
        #pragma unroll
        for (int p = 0; p < 2; p++) {
            const ulonglong2* v8 = (const ulonglong2*)(buf[p] + 808);
            const float* aT = alphaT[p];
            #pragma unroll
            for (int s = 0; s < G; s++) {
                float4 al = *(const float4*)&aT[s * 24 + d0];
                ulonglong2 vv = v8[s * 16 + c4];
                u64 pp;
                pp = pack2(al.x, al.x); acc[0][0] = fma2(pp, vv.x, acc[0][0]); acc[0][1] = fma2(pp, vv.y, acc[0][1]);
                pp = pack2(al.y, al.y); acc[1][0] = fma2(pp, vv.x, acc[1][0]); acc[1][1] = fma2(pp, vv.y, acc[1][1]);
                pp = pack2(al.z, al.z); acc[2][0] = fma2(pp, vv.x, acc[2][0]); acc[2][1] = fma2(pp, vv.y, acc[2][1]);
                pp = pack2(al.w, al.w); acc[3][0] = fma2(pp, vv.x, acc[3][0]); acc[3][1] = fma2(pp, vv.y, acc[3][1]);
            }
        }
        #pragma unroll
        for (int i2 = 0; i2 < 4; i2++) {
            float* dst = g_h + (size_t)(n0 + d0 + i2) * DH + c4 * 4;
            float x0, x1, x2, x3;
            unpack2(acc[i2][0], x0, x1);
            unpack2(acc[i2][1], x2, x3);
            atomicAdd(dst + 0, x0 * 0.125f);
            atomicAdd(dst + 1, x1 * 0.125f);
            atomicAdd(dst + 2, x2 * 0.125f);
            atomicAdd(dst + 3, x3 * 0.125f);
        }
    }
}

// ---------------- K5: h stats (96 blocks x 64 rows) -------------------------
__global__ void __launch_bounds__(256)
k_hstats() {
    __shared__ float smS[16 * 64], smQ[16 * 64];
    int t  = threadIdx.x;
    int c4 = t & 15;
    int rs = t >> 4;
    int r0 = blockIdx.x * 64;

    const float4* h4 = (const float4*)g_h;
    float4 s = make_float4(0.f, 0.f, 0.f, 0.f);
    float4 q = make_float4(0.f, 0.f, 0.f, 0.f);
    #pragma unroll
    for (int r = rs; r < 64; r += 16) {
        float4 a = h4[(size_t)(r0 + r) * 16 + c4];
        s.x += a.x; s.y += a.y; s.z += a.z; s.w += a.w;
        q.x += a.x * a.x; q.y += a.y * a.y; q.z += a.z * a.z; q.w += a.w * a.w;
    }
    ((float4*)smS)[rs * 16 + c4] = s;
    ((float4*)smQ)[rs * 16 + c4] = q;
    __syncthreads();
    if (t < 64) {
        float ss = 0.f, qq = 0.f;
        #pragma unroll
        for (int j = 0; j < 16; j++) { ss += smS[j * 64 + t]; qq += smQ[j * 64 + t]; }
        atomicAdd(&g_hsum[t], ss);
        atomicAdd(&g_hsumsq[t], qq);
    }
}

__device__ __forceinline__ float gelu_exact(float v) {
    return 0.5f * v * (1.0f + erff(v * 0.70710678118654752f));
}

// ---------------- K6: global norm + PFF + per-set norm + score + pooling ----
#define WPU 65
__global__ void __launch_bounds__(256)
k_final(const float* __restrict__ x,
        const float* __restrict__ no_w, const float* __restrict__ no_b,
        const float* __restrict__ no_ms,
        const float* __restrict__ o_w1, const float* __restrict__ o_b1,
        const float* __restrict__ o_w2, const float* __restrict__ o_b2,
        const float* __restrict__ pn_w, const float* __restrict__ pn_b,
        const float* __restrict__ pn_ms,
        const float* __restrict__ p_w1, const float* __restrict__ p_b1,
        const float* __restrict__ p_w2, const float* __restrict__ p_b2,
        float* __restrict__ out) {
    extern __shared__ float dsm[];
    u64*  w1P  = (u64*)dsm;
    u64*  w2P  = w1P + 32 * WPU;
    u64*  pw1P = w2P + 32 * WPU;
    u64*  pw2P = pw1P + 32 * WPU;
    float* hs  = (float*)(pw2P + 32);
    float* hn  = hs + G * DH;
    float* t1  = hn + G * DH;
    float* h2  = t1 + G * DH;
    float* a2  = h2 + G * DH;
    float* b2v = a2 + DH;
    float* cm  = b2v + DH;
    float* cr  = cm + DH;
    float* b1s = cr + DH;
    float* b2s = b1s + DH;
    float* pb1s = b2s + DH;
    float* score = pb1s + DH;
    float* wsf   = score + G;

    int tid = threadIdx.x;
    int n0  = blockIdx.x * G;

    for (int i = tid; i < 64 * 32; i += 256) {
        int j = i >> 5, c2 = i & 31;
        float2 w1v = *(const float2*)(o_w1 + j * 64 + c2 * 2);
        w1P[c2 * WPU + j] = pack2(w1v.x, w1v.y);
        float2 pw = *(const float2*)(p_w1 + j * 64 + c2 * 2);
        pw1P[c2 * WPU + j] = pack2(pw.x, pw.y);
        float2 w2v = *(const float2*)(o_w2 + j * 64 + c2 * 2);
        w2P[c2 * WPU + j] = pack2(w2v.x, w2v.y);
    }
    if (tid < 32) {
        pw2P[tid] = pack2(p_w2[tid * 2], p_w2[tid * 2 + 1]);
    }
    if (tid < DH) {
        b1s[tid] = o_b1[tid]; b2s[tid] = o_b2[tid];
        pb1s[tid] = p_b1[tid];
        const float invN = 1.0f / NN;
        float mean = g_hsum[tid] * invN;
        float ex2  = g_hsumsq[tid] * invN;
        float mm   = mean * no_ms[tid];
        float var  = ex2 - 2.f * mm * mean + mm * mm;
        float rinv = rsqrtf(var + 1e-5f);
        a2[tid] = no_w[tid] * rinv;
        b2v[tid] = no_b[tid] - no_w[tid] * rinv * mm;
    }
    for (int i = tid; i < G * DH; i += 256) hs[i] = g_h[(size_t)n0 * DH + i];
    __syncthreads();

    for (int i = tid; i < G * DH; i += 256) {
        int c = i & 63;
        hn[i] = fmaf(hs[i], a2[c], b2v[c]);
    }
    __syncthreads();

    for (int i = tid; i < 384; i += 256) {
        int dp = i >> 5, jp = i & 31, d0 = dp * 2;
        u64 A00 = 0, A01 = 0, A10 = 0, A11 = 0;
        const u64* h0 = (const u64*)(hn + d0 * DH);
        const u64* h1 = (const u64*)(hn + (d0 + 1) * DH);
        #pragma unroll 8
        for (int c2 = 0; c2 < 32; c2++) {
            u64 w0 = w1P[c2 * WPU + jp], w1 = w1P[c2 * WPU + jp + 32];
            u64 hc0 = h0[c2], hc1 = h1[c2];
            A00 = fma2(hc0, w0, A00); A01 = fma2(hc0, w1, A01);
            A10 = fma2(hc1, w0, A10); A11 = fma2(hc1, w1, A11);
        }
        float lo, hi;
        unpack2(A00, lo, hi); t1[d0 * DH + jp]            = gelu_exact(lo + hi + b1s[jp]);
        unpack2(A01, lo, hi); t1[d0 * DH + jp + 32]       = gelu_exact(lo + hi + b1s[jp + 32]);
        unpack2(A10, lo, hi); t1[(d0 + 1) * DH + jp]      = gelu_exact(lo + hi + b1s[jp]);
        unpack2(A11, lo, hi); t1[(d0 + 1) * DH + jp + 32] = gelu_exact(lo + hi + b1s[jp + 32]);
    }
    __syncthreads();

    for (int i = tid; i < 384; i += 256) {
        int dp = i >> 5, cp = i & 31, d0 = dp * 2;
        u64 A00 = 0, A01 = 0, A10 = 0, A11 = 0;
        const u64* t0 = (const u64*)(t1 + d0 * DH);
        const u64* t1r = (const u64*)(t1 + (d0 + 1) * DH);
        #pragma unroll 8
        for (int j2 = 0; j2 < 32; j2++) {
            u64 w0 = w2P[j2 * WPU + cp], w1 = w2P[j2 * WPU + cp + 32];
            u64 tc0 = t0[j2], tc1 = t1r[j2];
            A00 = fma2(tc0, w0, A00); A01 = fma2(tc0, w1, A01);
            A10 = fma2(tc1, w0, A10); A11 = fma2(tc1, w1, A11);
        }
        float lo, hi;
        unpack2(A00, lo, hi); h2[d0 * DH + cp]            = hs[d0 * DH + cp] + lo + hi + b2s[cp];
        unpack2(A01, lo, hi); h2[d0 * DH + cp + 32]       = hs[d0 * DH + cp + 32] + lo + hi + b2s[cp + 32];
        unpack2(A10, lo, hi); h2[(d0 + 1) * DH + cp]      = hs[(d0 + 1) * DH + cp] + lo + hi + b2s[cp];
        unpack2(A11, lo, hi); h2[(d0 + 1) * DH + cp + 32] = hs[(d0 + 1) * DH + cp + 32] + lo + hi + b2s[cp + 32];
    }
    __syncthreads();

    if (tid < DH) {
        int c = tid;
        float m = 0.f;
        #pragma unroll
        for (int d = 0; d < G; d++) m += h2[d * DH + c];
        m *= (1.0f / G);
        float mm = m * pn_ms[c];
        float vv = 0.f;
        #pragma unroll
        for (int d = 0; d < G; d++) { float t = h2[d * DH + c] - mm; vv += t * t; }
        vv *= (1.0f / G);
        cm[c] = mm;
        cr[c] = pn_w[c] * rsqrtf(vv + 1e-5f);
    }
    __syncthreads();

    for (int i = tid; i < G * DH; i += 256) {
        int c = i & 63;
        hn[i] = fmaf(h2[i] - cm[c], cr[c], pn_b[c]);
    }
    __syncthreads();

    for (int i = tid; i < 384; i += 256) {
        int dp = i >> 5, jp = i & 31, d0 = dp * 2;
        u64 A00 = 0, A01 = 0, A10 = 0, A11 = 0;
        const u64* h0 = (const u64*)(hn + d0 * DH);
        const u64* h1 = (const u64*)(hn + (d0 + 1) * DH);
        #pragma unroll 8
        for (int c2 = 0; c2 < 32; c2++) {
            u64 w0 = pw1P[c2 * WPU + jp], w1 = pw1P[c2 * WPU + jp + 32];
            u64 hc0 = h0[c2], hc1 = h1[c2];
            A00 = fma2(hc0, w0, A00); A01 = fma2(hc0, w1, A01);
            A10 = fma2(hc1, w0, A10); A11 = fma2(hc1, w1, A11);
        }
        float lo, hi;
        unpack2(A00, lo, hi); t1[d0 * DH + jp]            = gelu_exact(lo + hi + pb1s[jp]);
        unpack2(A01, lo, hi); t1[d0 * DH + jp + 32]       = gelu_exact(lo + hi + pb1s[jp + 32]);
        unpack2(A10, lo, hi); t1[(d0 + 1) * DH + jp]      = gelu_exact(lo + hi + pb1s[jp]);
        unpack2(A11, lo, hi); t1[(d0 + 1) * DH + jp + 32] = gelu_exact(lo + hi + pb1s[jp + 32]);
    }
    __syncthreads();

    if (tid < G) {
        const u64* tr = (const u64*)(t1 + tid * DH);
        u64 A = 0;
        #pragma unroll 8
        for (int j2 = 0; j2 < 32; j2++) A = fma2(tr[j2], pw2P[j2], A);
        float lo, hi;
        unpack2(A, lo, hi);
        score[tid] = lo + hi + p_b2[0];
    }
    __syncthreads();

    if (tid == 0) {
        float m = score[0];
        #pragma unroll
        for (int d = 1; d < G; d++) m = fmaxf(m, score[d]);
        float sum = 0.f;
        #pragma unroll
        for (int d = 0; d < G; d++) { wsf[d] = expf(score[d] - m); sum += wsf[d]; }
        float inv = 1.0f / (sum + 1e-16f);
        #pragma unroll
        for (int d = 0; d < G; d++) wsf[d] *= inv;
    }
    __syncthreads();

    if (tid < DIN) {
        float acc = 0.f;
        #pragma unroll
        for (int d = 0; d < G; d++)
            acc = fmaf(wsf[d], x[(size_t)(n0 + d) * DIN + tid], acc);
        out[blockIdx.x * DIN + tid] = acc;
    }
}

// ---------------- launch -----------------------------------------------------
extern "C" void kernel_launch(void* const* d_in, const int* in_sizes, int n_in,
                              void* d_out, int out_size) {
    const float* x     = (const float*)d_in[0];
    const float* nq_w  = (const float*)d_in[4];
    const float* nq_b  = (const float*)d_in[5];
    const float* nq_ms = (const float*)d_in[6];
    const float* wq    = (const float*)d_in[7];
    const float* bq    = (const float*)d_in[8];
    const float* wk    = (const float*)d_in[9];
    const float* bk    = (const float*)d_in[10];
    const float* wv    = (const float*)d_in[11];
    const float* bv    = (const float*)d_in[12];
    const float* no_w  = (const float*)d_in[13];
    const float* no_b  = (const float*)d_in[14];
    const float* no_ms = (const float*)d_in[15];
    const float* o_w1  = (const float*)d_in[16];
    const float* o_b1  = (const float*)d_in[17];
    const float* o_w2  = (const float*)d_in[18];
    const float* o_b2  = (const float*)d_in[19];
    const float* pn_w  = (const float*)d_in[20];
    const float* pn_b  = (const float*)d_in[21];
    const float* pn_ms = (const float*)d_in[22];
    const float* p_w1  = (const float*)d_in[23];
    const float* p_b1  = (const float*)d_in[24];
    const float* p_w2  = (const float*)d_in[25];
    const float* p_b2  = (const float*)d_in[26];
    float* out = (float*)d_out;

    const int smem_qkv = 512 + 2 * ATILE + 2 * BTILE;
    const int smem_fin = (3 * 32 * WPU + 32) * 8 + (4 * G * DH + 7 * DH + 2 * G) * 4;
    cudaFuncSetAttribute(k_qkv,   cudaFuncAttributeMaxDynamicSharedMemorySize, smem_qkv);
    cudaFuncSetAttribute(k_final, cudaFuncAttributeMaxDynamicSharedMemorySize, smem_fin);

    k_xstats<<<96, 256>>>(x);
    k_xnorm<<<60, 256>>>(x, nq_w, nq_b, nq_ms, wq, wk, wv);
    k_qkv<<<dim3(48, 24), 256, smem_qkv>>>(bq, bk, bv);
    k_attn<<<1024, 192>>>();
    k_hstats<<<96, 256>>>();
    k_final<<<256, 256, smem_fin>>>(x, no_w, no_b, no_ms,
                                    o_w1, o_b1, o_w2, o_b2,
                                    pn_w, pn_b, pn_ms,
                                    p_w1, p_b1, p_w2, p_b2, out);
}